// round 12
// baseline (speedup 1.0000x reference)
#include <cuda_runtime.h>
#include <cuda_bf16.h>
#include <mma.h>

using namespace nvcuda;

typedef __nv_bfloat16 bf16;

#define BS_TOK 4096
#define DMODEL 1024
#define NMEM   32768
#define DKEY   256
#define DVAL   1024
#define TOPK   32
#define NCAND  64
#define NCHUNK 512
#define TKCAP  8192

// ------------------------------ scratch (device globals) ------------------------------
__device__ __align__(16) float2 g_q2[BS_TOK * DKEY];
__device__ __align__(16) float  g_qn_hi[BS_TOK * DKEY];
__device__ __align__(16) float  g_qn_lo[BS_TOK * DKEY];
__device__ __align__(16) bf16   g_qb[BS_TOK * DKEY];
__device__ __align__(16) float  g_kn_hi[NMEM * DKEY];
__device__ __align__(16) float  g_kn_lo[NMEM * DKEY];
__device__ __align__(16) bf16   g_kb[NMEM * DKEY];
__device__ __align__(16) bf16   g_sims[(size_t)BS_TOK * NMEM];   // 256 MB
__device__ __align__(16) bf16   g_blkmax[BS_TOK * NCHUNK];       // 4 MB chunk maxima
__device__ int   g_cand[BS_TOK * NCAND];
__device__ float g_w[BS_TOK * TOPK];
__device__ int   g_widx[BS_TOK * TOPK];
__device__ __align__(16) float g_memout[BS_TOK * DVAL];
__device__ __align__(16) bf16 g_xhi[BS_TOK * DMODEL];
__device__ __align__(16) bf16 g_xlo[BS_TOK * DMODEL];
__device__ __align__(16) bf16 g_wghi[DVAL * DMODEL];
__device__ __align__(16) bf16 g_wglo[DVAL * DMODEL];
__device__ __align__(16) bf16 g_wohi[DMODEL * DVAL];
__device__ __align__(16) bf16 g_wolo[DMODEL * DVAL];
__device__ __align__(16) bf16 g_hhi[BS_TOK * DVAL];
__device__ __align__(16) bf16 g_hlo[BS_TOK * DVAL];

// ------------------------------ split x / weights -> bf16 hi/lo ------------------------------
#define NX (BS_TOK * DMODEL)
#define NWG (DVAL * DMODEL)
#define NWO (DMODEL * DVAL)

__global__ void splitx_kernel(const float* __restrict__ x) {
    int i = blockIdx.x * blockDim.x + threadIdx.x;
    if (i >= NX) return;
    float v = x[i];
    bf16 h = __float2bfloat16(v);
    g_xhi[i] = h;
    g_xlo[i] = __float2bfloat16(__fadd_rn(v, -__bfloat162float(h)));
}

__global__ void splitw_kernel(const float* __restrict__ wg,
                              const float* __restrict__ wo) {
    int i = blockIdx.x * blockDim.x + threadIdx.x;
    const float* src; bf16 *hi, *lo; int j;
    if (i < NWG) { src = wg; hi = g_wghi; lo = g_wglo; j = i; }
    else if (i < NWG + NWO) { src = wo; hi = g_wohi; lo = g_wolo; j = i - NWG; }
    else return;
    float v = src[j];
    bf16 h = __float2bfloat16(v);
    hi[j] = h;
    lo[j] = __float2bfloat16(__fadd_rn(v, -__bfloat162float(h)));
}

// ------------------------------ key normalize (double-float fp32) ------------------------------
__global__ __launch_bounds__(256) void knorm_kernel(const float* __restrict__ keys) {
    int row = blockIdx.x * 8 + (threadIdx.x >> 5);
    int lane = threadIdx.x & 31;
    const float4* s4 = (const float4*)(keys + (size_t)row * DKEY);
    float4 a = s4[lane], b = s4[lane + 32];
    float v[8] = {a.x, a.y, a.z, a.w, b.x, b.y, b.z, b.w};

    float s = 0.f, c = 0.f;
    #pragma unroll
    for (int i = 0; i < 8; i++) {
        float p = __fmul_rn(v[i], v[i]);
        float e = __fmaf_rn(v[i], v[i], -p);
        float t  = __fadd_rn(s, p);
        float bv = __fadd_rn(t, -s);
        float err = __fadd_rn(__fadd_rn(s, -__fadd_rn(t, -bv)), __fadd_rn(p, -bv));
        s = t;
        c = __fadd_rn(c, __fadd_rn(err, e));
    }
    double d = (double)s + (double)c;
    #pragma unroll
    for (int o = 16; o; o >>= 1) d += __shfl_xor_sync(0xffffffffu, d, o);
    double inv = 1.0 / fmax(sqrt(d), 1e-12);
    float ih = (float)inv;
    float il = (float)(inv - (double)ih);

    float h2[8], l2[8];
    #pragma unroll
    for (int i = 0; i < 8; i++) {
        float p = __fmul_rn(v[i], ih);
        float e = __fmaf_rn(v[i], ih, -p);
        float lo = __fmaf_rn(v[i], il, e);
        float hh = __fadd_rn(p, lo);
        h2[i] = hh;
        l2[i] = __fadd_rn(lo, -__fadd_rn(hh, -p));
    }
    float4* dh = (float4*)(g_kn_hi + (size_t)row * DKEY);
    float4* dl = (float4*)(g_kn_lo + (size_t)row * DKEY);
    dh[lane]      = make_float4(h2[0], h2[1], h2[2], h2[3]);
    dh[lane + 32] = make_float4(h2[4], h2[5], h2[6], h2[7]);
    dl[lane]      = make_float4(l2[0], l2[1], l2[2], l2[3]);
    dl[lane + 32] = make_float4(l2[4], l2[5], l2[6], l2[7]);
    __nv_bfloat162* db = (__nv_bfloat162*)(g_kb + (size_t)row * DKEY);
    db[lane*2 + 0]  = __nv_bfloat162(__float2bfloat16(h2[0]), __float2bfloat16(h2[1]));
    db[lane*2 + 1]  = __nv_bfloat162(__float2bfloat16(h2[2]), __float2bfloat16(h2[3]));
    db[64 + lane*2 + 0] = __nv_bfloat162(__float2bfloat16(h2[4]), __float2bfloat16(h2[5]));
    db[64 + lane*2 + 1] = __nv_bfloat162(__float2bfloat16(h2[6]), __float2bfloat16(h2[7]));
}

// ------------------------------ exact q GEMM v2: 32x32 tile, 1024 blocks, offset-accumulator ------------------------------
#define QTM 32
#define QTN 32
#define QTK 32
#define QOFF 1024.0f

__global__ __launch_bounds__(256) void qexact_kernel(const float* __restrict__ x,
                                                     const float* __restrict__ wq) {
    __shared__ float sX[QTK][QTM + 4];
    __shared__ float sW[QTK][QTN + 4];
    int bt = blockIdx.y * QTM;
    int bq = blockIdx.x * QTN;
    int tid = threadIdx.x;
    int ty = tid >> 4;
    int tx = tid & 15;

    float A[2][2], A2[2][2];
    #pragma unroll
    for (int i = 0; i < 2; i++)
        #pragma unroll
        for (int j = 0; j < 2; j++) { A[i][j] = QOFF; A2[i][j] = 0.f; }

    int lrow = tid >> 3;
    int lc4 = (tid & 7) * 4;

    for (int kc = 0; kc < DMODEL; kc += QTK) {
        float4 v = *(const float4*)(x + (size_t)(bt + lrow) * DMODEL + kc + lc4);
        sX[lc4+0][lrow] = v.x; sX[lc4+1][lrow] = v.y;
        sX[lc4+2][lrow] = v.z; sX[lc4+3][lrow] = v.w;
        float4 w = *(const float4*)(wq + (size_t)(bq + lrow) * DMODEL + kc + lc4);
        sW[lc4+0][lrow] = w.x; sW[lc4+1][lrow] = w.y;
        sW[lc4+2][lrow] = w.z; sW[lc4+3][lrow] = w.w;
        __syncthreads();
        #pragma unroll 8
        for (int k = 0; k < QTK; k++) {
            float2 rx = *(const float2*)&sX[k][ty * 2];
            float2 rw = *(const float2*)&sW[k][tx * 2];
            float ax[2] = {rx.x, rx.y};
            float bw[2] = {rw.x, rw.y};
            #pragma unroll
            for (int i = 0; i < 2; i++)
                #pragma unroll
                for (int j = 0; j < 2; j++) {
                    float p = __fmul_rn(ax[i], bw[j]);
                    float e = __fmaf_rn(ax[i], bw[j], -p);
                    float t = __fadd_rn(A[i][j], p);
                    float z = __fadd_rn(t, -A[i][j]);
                    float r = __fadd_rn(p, -z);
                    A[i][j] = t;
                    A2[i][j] = __fadd_rn(A2[i][j], __fadd_rn(r, e));
                }
        }
        __syncthreads();
    }

    #pragma unroll
    for (int i = 0; i < 2; i++)
        #pragma unroll
        for (int j = 0; j < 2; j++) {
            double sum = (double)__fadd_rn(A[i][j], -QOFF) + (double)A2[i][j];
            float hi = (float)sum;
            float lo = (float)(sum - (double)hi);
            g_q2[(size_t)(bt + ty*2 + i) * DKEY + (bq + tx*2 + j)] = make_float2(hi, lo);
        }
}

// ------------------------------ q normalize (fp64, ILP) ------------------------------
__global__ void qnorm_kernel() {
    int row = blockIdx.x * 8 + (threadIdx.x >> 5);
    int lane = threadIdx.x & 31;
    const float2* q = g_q2 + (size_t)row * DKEY;
    double v[8];
    double s0 = 0.0, s1 = 0.0, s2 = 0.0, s3 = 0.0;
    #pragma unroll
    for (int i = 0; i < 8; i += 4) {
        float2 p0 = q[lane + i * 32];
        float2 p1 = q[lane + (i+1) * 32];
        float2 p2 = q[lane + (i+2) * 32];
        float2 p3 = q[lane + (i+3) * 32];
        v[i]   = (double)p0.x + (double)p0.y;
        v[i+1] = (double)p1.x + (double)p1.y;
        v[i+2] = (double)p2.x + (double)p2.y;
        v[i+3] = (double)p3.x + (double)p3.y;
        s0 = fma(v[i], v[i], s0);
        s1 = fma(v[i+1], v[i+1], s1);
        s2 = fma(v[i+2], v[i+2], s2);
        s3 = fma(v[i+3], v[i+3], s3);
    }
    double ss = (s0 + s1) + (s2 + s3);
    #pragma unroll
    for (int o = 16; o; o >>= 1) ss += __shfl_xor_sync(0xffffffffu, ss, o);
    double inv = 1.0 / fmax(sqrt(ss), 1e-12);
    #pragma unroll
    for (int i = 0; i < 8; i++) {
        double qn = v[i] * inv;
        float hi = (float)qn;
        float lo = (float)(qn - (double)hi);
        size_t gi = (size_t)row * DKEY + lane + i * 32;
        g_qn_hi[gi] = hi;
        g_qn_lo[gi] = lo;
        g_qb[gi] = __float2bfloat16(hi);
    }
}

// ------------------------------ sims GEMM v3: 128x128 tile, 512 threads (16 warps), full-K ------------------------------
#define SBM 128
#define SBN 128
#define SPAD 264
#define SIMS_SMEM ((SBM + SBN) * SPAD * 2)

__global__ __launch_bounds__(512, 1) void sims_kernel() {
    extern __shared__ char smem_raw[];
    bf16* sQ = (bf16*)smem_raw;                       // 128 x 264
    bf16* sK = sQ + SBM * SPAD;                       // 128 x 264
    float* stagef = (float*)smem_raw;                 // epilogue overlay: 128 x 132 fp32

    int bm = blockIdx.y * SBM;
    int bn = blockIdx.x * SBN;
    int tid = threadIdx.x;
    int warp = tid >> 5;
    int wr = warp >> 2;       // 0..3 -> 32-row band
    int wc = warp & 3;        // 0..3 -> 32-col band

    // load Q tile: 128 rows x 32 float4 groups = 4096 items / 512 threads = 8 reps
    #pragma unroll
    for (int rep = 0; rep < 8; rep++) {
        int idx = tid + rep * 512;
        int row = idx >> 5, g = idx & 31;
        *(float4*)(sQ + row * SPAD + g * 8) =
            *(const float4*)(g_qb + (size_t)(bm + row) * DKEY + g * 8);
    }
    // load K tile
    #pragma unroll
    for (int rep = 0; rep < 8; rep++) {
        int idx = tid + rep * 512;
        int row = idx >> 5, g = idx & 31;
        *(float4*)(sK + row * SPAD + g * 8) =
            *(const float4*)(g_kb + (size_t)(bn + row) * DKEY + g * 8);
    }
    __syncthreads();

    wmma::fragment<wmma::accumulator, 16, 16, 16, float> acc[2][2];
    #pragma unroll
    for (int i = 0; i < 2; i++)
        #pragma unroll
        for (int j = 0; j < 2; j++) wmma::fill_fragment(acc[i][j], 0.0f);

    #pragma unroll
    for (int ks = 0; ks < DKEY / 16; ks++) {
        int kc = ks * 16;
        wmma::fragment<wmma::matrix_a, 16, 16, 16, bf16, wmma::row_major> a[2];
        wmma::fragment<wmma::matrix_b, 16, 16, 16, bf16, wmma::col_major> b[2];
        #pragma unroll
        for (int i = 0; i < 2; i++)
            wmma::load_matrix_sync(a[i], sQ + (wr * 32 + i * 16) * SPAD + kc, SPAD);
        #pragma unroll
        for (int j = 0; j < 2; j++)
            wmma::load_matrix_sync(b[j], sK + (wc * 32 + j * 16) * SPAD + kc, SPAD);
        #pragma unroll
        for (int i = 0; i < 2; i++)
            #pragma unroll
            for (int j = 0; j < 2; j++)
                wmma::mma_sync(acc[i][j], a[i], b[j], acc[i][j]);
    }
    __syncthreads();   // done reading smem tiles; overlay epilogue stage

    #pragma unroll
    for (int i = 0; i < 2; i++)
        #pragma unroll
        for (int j = 0; j < 2; j++)
            wmma::store_matrix_sync(stagef + (wr * 32 + i * 16) * 132 + wc * 32 + j * 16,
                                    acc[i][j], 132, wmma::mem_row_major);
    __syncthreads();

    // convert + coalesced write + per-64-key chunk maxima
    // idx: row = idx>>4 (128 rows), g = idx&15 (16 groups of 8 cols); 2048 items / 512 = 4 reps
    #pragma unroll
    for (int rep = 0; rep < 4; rep++) {
        int idx = tid + rep * 512;
        int row = idx >> 4, g = idx & 15;
        const float* src = stagef + row * 132 + g * 8;
        float4 f0 = *(const float4*)src;
        float4 f1 = *(const float4*)(src + 4);
        __align__(16) bf16 tmp[8];
        tmp[0] = __float2bfloat16(f0.x); tmp[1] = __float2bfloat16(f0.y);
        tmp[2] = __float2bfloat16(f0.z); tmp[3] = __float2bfloat16(f0.w);
        tmp[4] = __float2bfloat16(f1.x); tmp[5] = __float2bfloat16(f1.y);
        tmp[6] = __float2bfloat16(f1.z); tmp[7] = __float2bfloat16(f1.w);
        *(float4*)(g_sims + (size_t)(bm + row) * NMEM + bn + g * 8) = *(float4*)tmp;

        float mx = __bfloat162float(tmp[0]);
        #pragma unroll
        for (int e = 1; e < 8; e++) mx = fmaxf(mx, __bfloat162float(tmp[e]));
        // lanes 0..7 / 8..15 / 16..23 / 24..31 each form one 64-col chunk (same row)
        #pragma unroll
        for (int off = 1; off < 8; off <<= 1)
            mx = fmaxf(mx, __shfl_xor_sync(0xffffffffu, mx, off));
        if ((g & 7) == 0)
            g_blkmax[(size_t)(bm + row) * NCHUNK + (bn >> 6) + (g >> 3)] = __float2bfloat16(mx);
    }
}

// ------------------------------ top-64 preselect v3: chunk-max pruning, small smem ------------------------------
__device__ __forceinline__ unsigned ordkey16(unsigned u) {
    return (u & 0x8000u) ? (u ^ 0xFFFFu) : (u | 0x8000u);
}

__global__ __launch_bounds__(256) void topk_kernel() {
    int t = blockIdx.x;
    extern __shared__ unsigned short sbuf[];        // TKCAP ordkeys = 16 KB
    __shared__ unsigned short sclist[NCHUNK];
    __shared__ unsigned hist[256];
    __shared__ unsigned sh_b, sh_above, sh_KM, sh_nsel, sh_thr, sh_K1, ctrG, ctrE;
    int tid = threadIdx.x;

    hist[tid] = 0;
    __syncthreads();
    unsigned mk0, mk1;
    {
        const unsigned short* bm = (const unsigned short*)(g_blkmax + (size_t)t * NCHUNK);
        mk0 = ordkey16((unsigned)bm[tid]);
        mk1 = ordkey16((unsigned)bm[tid + 256]);
        atomicAdd(&hist[mk0 >> 8], 1u);
        atomicAdd(&hist[mk1 >> 8], 1u);
    }
    __syncthreads();
    if (tid == 0) {
        unsigned cum = 0; int b = 255;
        for (; b > 0; b--) { if (cum + hist[b] >= NCAND) break; cum += hist[b]; }
        sh_b = (unsigned)b; sh_above = cum;
    }
    __syncthreads();
    unsigned b = sh_b;
    hist[tid] = 0;
    __syncthreads();
    if ((mk0 >> 8) == b) atomicAdd(&hist[mk0 & 255u], 1u);
    if ((mk1 >> 8) == b) atomicAdd(&hist[mk1 & 255u], 1u);
    __syncthreads();
    if (tid == 0) {
        unsigned cum = sh_above; int l = 255;
        for (; l > 0; l--) { if (cum + hist[l] >= NCAND) break; cum += hist[l]; }
        sh_KM = (b << 8) | (unsigned)l;
        sh_nsel = 0;
    }
    __syncthreads();

    unsigned KM = sh_KM;
    if (mk0 >= KM) { unsigned p = atomicAdd(&sh_nsel, 1u); sclist[p] = (unsigned short)tid; }
    if (mk1 >= KM) { unsigned p = atomicAdd(&sh_nsel, 1u); sclist[p] = (unsigned short)(tid + 256); }
    __syncthreads();
    int ns = (int)sh_nsel * 64;

    hist[tid] = 0;
    __syncthreads();
    const unsigned short* row = (const unsigned short*)(g_sims + (size_t)t * NMEM);
    for (int j = tid; j < ns; j += 256) {
        int chunk = sclist[j >> 6];
        unsigned k = ordkey16((unsigned)row[chunk * 64 + (j & 63)]);
        if (j < TKCAP) sbuf[j] = (unsigned short)k;
        atomicAdd(&hist[k >> 8], 1u);
    }
    __syncthreads();
    if (tid == 0) {
        unsigned cum = 0; int bb = 255;
        for (; bb > 0; bb--) { if (cum + hist[bb] >= NCAND) break; cum += hist[bb]; }
        sh_b = (unsigned)bb; sh_above = cum;
    }
    __syncthreads();
    unsigned b2 = sh_b;
    hist[tid] = 0;
    __syncthreads();
    for (int j = tid; j < ns; j += 256) {
        unsigned k = (j < TKCAP) ? (unsigned)sbuf[j]
                   : ordkey16((unsigned)row[sclist[j >> 6] * 64 + (j & 63)]);
        if ((k >> 8) == b2) atomicAdd(&hist[k & 255u], 1u);
    }
    __syncthreads();
    if (tid == 0) {
        unsigned cum = sh_above; int l = 255;
        for (; l > 0; l--) { if (cum + hist[l] >= NCAND) break; cum += hist[l]; }
        sh_thr = (b2 << 8) | (unsigned)l;
        sh_K1 = cum;
        ctrG = 0; ctrE = 0;
    }
    __syncthreads();

    unsigned thr = sh_thr, K1 = sh_K1;
    for (int j = tid; j < ns; j += 256) {
        unsigned k = (j < TKCAP) ? (unsigned)sbuf[j]
                   : ordkey16((unsigned)row[sclist[j >> 6] * 64 + (j & 63)]);
        if (k > thr) {
            unsigned p = atomicAdd(&ctrG, 1u);
            g_cand[t * NCAND + p] = (int)sclist[j >> 6] * 64 + (j & 63);
        } else if (k == thr) {
            unsigned p = atomicAdd(&ctrE, 1u);
            if (K1 + p < NCAND) g_cand[t * NCAND + K1 + p] = (int)sclist[j >> 6] * 64 + (j & 63);
        }
    }
}

// ------------------------------ exact double-float rescore + top-32 + softmax ------------------------------
__device__ __forceinline__ void kmac(float a, float b, float& s, float& c) {
    float p  = __fmul_rn(a, b);
    float e  = __fmaf_rn(a, b, -p);
    float t  = __fadd_rn(s, p);
    float bv = __fadd_rn(t, -s);
    float e1 = __fadd_rn(s, -__fadd_rn(t, -bv));
    float e2 = __fadd_rn(p, -bv);
    s = t;
    c = __fadd_rn(c, __fadd_rn(e, __fadd_rn(e1, e2)));
}

__global__ __launch_bounds__(256) void rescore_kernel() {
    int t = blockIdx.x;
    int tid = threadIdx.x;
    __shared__ __align__(16) float qhi[DKEY];
    __shared__ __align__(16) float qlo[DKEY];
    __shared__ float cval[NCAND];
    __shared__ int cidx[NCAND];
    __shared__ float sval[TOPK];
    __shared__ int sidx[TOPK];

    qhi[tid] = g_qn_hi[(size_t)t * DKEY + tid];
    qlo[tid] = g_qn_lo[(size_t)t * DKEY + tid];
    if (tid < NCAND) cidx[tid] = g_cand[t * NCAND + tid];
    __syncthreads();

    int c = tid >> 2, part = tid & 3;
    int ki = cidx[c];
    const float* khi = g_kn_hi + (size_t)ki * DKEY + part * 64;
    const float* klo = g_kn_lo + (size_t)ki * DKEY + part * 64;
    const float* qh = qhi + part * 64;
    const float* ql = qlo + part * 64;

    float s = 0.f, comp = 0.f, cr = 0.f;
    #pragma unroll 8
    for (int i = 0; i < 64; i++) {
        float kh = khi[i], kl = klo[i];
        float qhv = qh[i], qlv = ql[i];
        kmac(qhv, kh, s, comp);
        cr = __fmaf_rn(qhv, kl, cr);
        cr = __fmaf_rn(qlv, kh, cr);
    }
    double v = (double)s + (double)comp + (double)cr;
    v += __shfl_xor_sync(0xffffffffu, v, 1);
    v += __shfl_xor_sync(0xffffffffu, v, 2);
    if (part == 0) cval[c] = (float)v;
    __syncthreads();

    if (tid < NCAND) {
        float val = cval[tid]; int myi = cidx[tid];
        int rnk = 0;
        #pragma unroll 8
        for (int j = 0; j < NCAND; j++) {
            float u = cval[j];
            rnk += (u > val) || (u == val && cidx[j] < myi);
        }
        if (rnk < TOPK) { sval[rnk] = val; sidx[rnk] = myi; }
    }
    __syncthreads();

    if (tid < 32) {
        float val = sval[tid];
        float m = val;
        #pragma unroll
        for (int o = 16; o; o >>= 1) m = fmaxf(m, __shfl_xor_sync(0xffffffffu, m, o));
        float e = expf(val - m);
        float sum = e;
        #pragma unroll
        for (int o = 16; o; o >>= 1) sum += __shfl_xor_sync(0xffffffffu, sum, o);
        g_w[t * TOPK + tid] = e / sum;
        g_widx[t * TOPK + tid] = sidx[tid];
    }
}

// ------------------------------ weighted values gather ------------------------------
__global__ void gather_kernel(const float* __restrict__ values) {
    int t = blockIdx.x, tid = threadIdx.x;
    __shared__ float w[TOPK];
    __shared__ int idx[TOPK];
    if (tid < TOPK) { w[tid] = g_w[t * TOPK + tid]; idx[tid] = g_widx[t * TOPK + tid]; }
    __syncthreads();
    float4 acc = make_float4(0.f, 0.f, 0.f, 0.f);
    #pragma unroll 8
    for (int i = 0; i < TOPK; i++) {
        const float4 v = *((const float4*)(values + (size_t)idx[i] * DVAL) + tid);
        float wi = w[i];
        acc.x = fmaf(wi, v.x, acc.x);
        acc.y = fmaf(wi, v.y, acc.y);
        acc.z = fmaf(wi, v.z, acc.z);
        acc.w = fmaf(wi, v.w, acc.w);
    }
    ((float4*)(g_memout + (size_t)t * DVAL))[tid] = acc;
}

// ------------------------------ 3-term split-bf16 GEMM, double-buffered ------------------------------
template<int WHICH>
__global__ __launch_bounds__(256) void gemm_kernel(float* __restrict__ Cout) {
    constexpr int N = (WHICH == 1) ? DVAL : DMODEL;
    constexpr int K = (WHICH == 2) ? DVAL : DMODEL;
    constexpr int BM = 128, BN = 64, KC = 16;
    constexpr int NIT = K / KC;

    const bf16* Ahi = (WHICH == 2) ? g_hhi : g_xhi;
    const bf16* Alo = (WHICH == 2) ? g_hlo : g_xlo;
    const bf16* Bhi = (WHICH == 1) ? g_wghi : g_wohi;
    const bf16* Blo = (WHICH == 1) ? g_wglo : g_wolo;

    extern __shared__ char smem_raw[];
    bf16* sbuf = (bf16*)smem_raw;
    float* stage = (float*)smem_raw;

    int bm = blockIdx.y * BM;
    int bn = blockIdx.x * BN;
    int tid = threadIdx.x;
    int warp = tid >> 5;
    int wr = warp >> 1;
    int wc = warp & 1;

    wmma::fragment<wmma::accumulator, 16, 16, 16, float> acc[2][2];
    #pragma unroll
    for (int i = 0; i < 2; i++)
        #pragma unroll
        for (int j = 0; j < 2; j++) wmma::fill_fragment(acc[i][j], 0.0f);

    int ar = tid >> 1, ah = (tid & 1) * 8;
    int br = tid >> 2, bh2 = (tid & 3);

    const int OAH = 0, OAL = 2048, OBH = 4096, OBL = 5120;

    {
        const float4 va = *(const float4*)(Ahi + (size_t)(bm + ar) * K + ah);
        const float4 vb = *(const float4*)(Alo + (size_t)(bm + ar) * K + ah);
        *(float4*)(sbuf + OAH + ar * KC + ah) = va;
        *(float4*)(sbuf + OAL + ar * KC + ah) = vb;
        const bf16* bsrc = (bh2 & 2) ? Blo : Bhi;
        int bofs = (bh2 & 1) * 8;
        const float4 vc = *(const float4*)(bsrc + (size_t)(bn + br) * K + bofs);
        *(float4*)(sbuf + ((bh2 & 2) ? OBL : OBH) + br * KC + bofs) = vc;
    }
    __syncthreads();

    #pragma unroll 4
    for (int it = 0; it < NIT; it++) {
        int cur = (it & 1) * 6144;
        float4 pa, pal, pb;
        if (it + 1 < NIT) {
            int kc = (it + 1) * KC;
            pa  = *(const float4*)(Ahi + (size_t)(bm + ar) * K + kc + ah);
            pal = *(const float4*)(Alo + (size_t)(bm + ar) * K + kc + ah);
            const bf16* bsrc = (bh2 & 2) ? Blo : Bhi;
            pb  = *(const float4*)(bsrc + (size_t)(bn + br) * K + kc + (bh2 & 1) * 8);
        }

        wmma::fragment<wmma::matrix_a, 16, 16, 16, bf16, wmma::row_major> a0, a1, c0, c1;
        wmma::fragment<wmma::matrix_b, 16, 16, 16, bf16, wmma::col_major> b0, b1;

        wmma::load_matrix_sync(a0, sbuf + cur + OAH + (wr * 32 + 0) * KC, KC);
        wmma::load_matrix_sync(a1, sbuf + cur + OAH + (wr * 32 + 16) * KC, KC);
        wmma::load_matrix_sync(b0, sbuf + cur + OBH + (wc * 32 + 0) * KC, KC);
        wmma::load_matrix_sync(b1, sbuf + cur + OBH + (wc * 32 + 16) * KC, KC);
        wmma::mma_sync(acc[0][0], a0, b0, acc[0][0]);
        wmma::mma_sync(acc[0][1], a0, b1, acc[0][1]);
        wmma::mma_sync(acc[1][0], a1, b0, acc[1][0]);
        wmma::mma_sync(acc[1][1], a1, b1, acc[1][1]);

        wmma::load_matrix_sync(c0, sbuf + cur + OAL + (wr * 32 + 0) * KC, KC);
        wmma::load_matrix_sync(c1, sbuf + cur + OAL + (wr * 32 + 16) * KC, KC);
        wmma::mma_sync(acc[0][0], c0, b0, acc[0][0]);
        wmma::mma_sync(acc[0][1], c0, b1, acc[0][1]);
        wmma::mma_sync(acc[1][0], c1, b0, acc[1][0]);
        wmma::mma_sync(acc[1][1], c1, b1, acc[1][1]);

        wmma::load_matrix_sync(b0, sbuf + cur + OBL + (wc * 32 + 0) * KC, KC);
        wmma::load_matrix_sync(b1, sbuf + cur + OBL + (wc * 32 + 16) * KC, KC);
        wmma::mma_sync(acc[0][0], a0, b0, acc[0][0]);
        wmma::mma_sync(acc[0][1], a0, b1, acc[0][1]);
        wmma::mma_sync(acc[1][0], a1, b0, acc[1][0]);
        wmma::mma_sync(acc[1][1], a1, b1, acc[1][1]);

        if (it + 1 < NIT) {
            int nxt = ((it + 1) & 1) * 6144;
            *(float4*)(sbuf + nxt + OAH + ar * KC + ah) = pa;
            *(float4*)(sbuf + nxt + OAL + ar * KC + ah) = pal;
            *(float4*)(sbuf + nxt + ((bh2 & 2) ? OBL : OBH) + br * KC + (bh2 & 1) * 8) = pb;
            __syncthreads();
        }
    }

    if (WHICH == 2) {
        #pragma unroll
        for (int i = 0; i < 2; i++)
            #pragma unroll
            for (int j = 0; j < 2; j++)
                wmma::store_matrix_sync(Cout + (size_t)(bm + wr * 32 + i * 16) * N + bn + wc * 32 + j * 16,
                                        acc[i][j], N, wmma::mem_row_major);
    } else {
        __syncthreads();
        #pragma unroll
        for (int i = 0; i < 2; i++)
            #pragma unroll
            for (int j = 0; j < 2; j++)
                wmma::store_matrix_sync(stage + (wr * 32 + i * 16) * 68 + wc * 32 + j * 16,
                                        acc[i][j], 68, wmma::mem_row_major);
        __syncthreads();
        for (int e = tid; e < BM * BN; e += 256) {
            int lr = e >> 6, lc = e & 63;
            float gpre = stage[lr * 68 + lc];
            float sg = gpre / (1.0f + expf(-gpre));
            size_t gi = (size_t)(bm + lr) * N + bn + lc;
            float h = sg * g_memout[gi];
            bf16 hh = __float2bfloat16(h);
            g_hhi[gi] = hh;
            g_hlo[gi] = __float2bfloat16(h - __bfloat162float(hh));
        }
    }
}

// ------------------------------ launcher ------------------------------
extern "C" void kernel_launch(void* const* d_in, const int* in_sizes, int n_in,
                              void* d_out, int out_size) {
    const float *x = nullptr, *keys = nullptr, *values = nullptr,
                *w_q = nullptr, *w_gate = nullptr, *w_out = nullptr;
    for (int i = 0; i < n_in; i++) {
        int sz = in_sizes[i];
        const float* p = (const float*)d_in[i];
        if (sz == BS_TOK * DMODEL)      x = p;
        else if (sz == NMEM * DKEY)     keys = p;
        else if (sz == NMEM * DVAL)     values = p;
        else if (sz == DKEY * DMODEL)   w_q = p;
        else if (sz == DVAL * DMODEL) { if (!w_gate) w_gate = p; else w_out = p; }
    }
    float* out = (float*)d_out;

    cudaFuncSetAttribute(sims_kernel, cudaFuncAttributeMaxDynamicSharedMemorySize, SIMS_SMEM);

    size_t smem_g2 = 2 * 6144 * sizeof(bf16);                            // 24576 B
    size_t smem_g1 = (size_t)128 * 68 * sizeof(float);                   // 34816 B
    size_t smem_tk = TKCAP * 2;                                          // 16384 B

    // launch order: #4 = sims v3 (profiled; verify occupancy/tensor prediction)
    knorm_kernel<<<NMEM / 8, 256>>>(keys);                                   // 1
    qexact_kernel<<<dim3(DKEY / QTN, BS_TOK / QTM), 256>>>(x, w_q);          // 2
    qnorm_kernel<<<BS_TOK / 8, 256>>>();                                     // 3
    sims_kernel<<<dim3(NMEM / SBN, BS_TOK / SBM), 512, SIMS_SMEM>>>();       // 4 <- profiled
    splitx_kernel<<<(NX + 255) / 256, 256>>>(x);                             // 5
    splitw_kernel<<<(NWG + NWO + 255) / 256, 256>>>(w_gate, w_out);          // 6
    topk_kernel<<<BS_TOK, 256, smem_tk>>>();                                 // 7
    rescore_kernel<<<BS_TOK, 256>>>();                                       // 8
    gather_kernel<<<BS_TOK, 256>>>(values);                                  // 9
    gemm_kernel<1><<<dim3(DVAL / 64, BS_TOK / 128), 256, smem_g1>>>(nullptr);// 10
    gemm_kernel<2><<<dim3(DMODEL / 64, BS_TOK / 128), 256, smem_g2>>>(out);  // 11
}

// round 13
// speedup vs baseline: 1.0114x; 1.0114x over previous
#include <cuda_runtime.h>
#include <cuda_bf16.h>
#include <mma.h>

using namespace nvcuda;

typedef __nv_bfloat16 bf16;

#define BS_TOK 4096
#define DMODEL 1024
#define NMEM   32768
#define DKEY   256
#define DVAL   1024
#define TOPK   32
#define NCAND  64
#define NCHUNK 512
#define TKCAP  8192

// ------------------------------ scratch (device globals) ------------------------------
__device__ __align__(16) float2 g_q2[BS_TOK * DKEY];
__device__ __align__(16) float  g_qn_hi[BS_TOK * DKEY];
__device__ __align__(16) float  g_qn_lo[BS_TOK * DKEY];
__device__ __align__(16) bf16   g_qb[BS_TOK * DKEY];
__device__ __align__(16) float  g_kn_hi[NMEM * DKEY];
__device__ __align__(16) float  g_kn_lo[NMEM * DKEY];
__device__ __align__(16) bf16   g_kb[NMEM * DKEY];
__device__ __align__(16) bf16   g_sims[(size_t)BS_TOK * NMEM];   // 256 MB
__device__ __align__(16) bf16   g_blkmax[BS_TOK * NCHUNK];       // 4 MB chunk maxima
__device__ int   g_cand[BS_TOK * NCAND];
__device__ float g_w[BS_TOK * TOPK];
__device__ int   g_widx[BS_TOK * TOPK];
__device__ __align__(16) float g_memout[BS_TOK * DVAL];
__device__ __align__(16) bf16 g_xhi[BS_TOK * DMODEL];
__device__ __align__(16) bf16 g_xlo[BS_TOK * DMODEL];
__device__ __align__(16) bf16 g_wghi[DVAL * DMODEL];
__device__ __align__(16) bf16 g_wglo[DVAL * DMODEL];
__device__ __align__(16) bf16 g_wohi[DMODEL * DVAL];
__device__ __align__(16) bf16 g_wolo[DMODEL * DVAL];
__device__ __align__(16) bf16 g_hhi[BS_TOK * DVAL];
__device__ __align__(16) bf16 g_hlo[BS_TOK * DVAL];

#define NX (BS_TOK * DMODEL)
#define NWG (DVAL * DMODEL)
#define NWO (DMODEL * DVAL)

// ------------------------------ fused prep: knorm + splitx + splitw (all independent, light) ------------------------------
#define KNB (NMEM / 8)          // 4096 knorm blocks
#define NXB (NX / 256)          // 16384 splitx blocks
#define NWB ((NWG + NWO) / 256) // 8192 splitw blocks

__global__ __launch_bounds__(256) void prep_kernel(const float* __restrict__ keys,
                                                   const float* __restrict__ x,
                                                   const float* __restrict__ wg,
                                                   const float* __restrict__ wo) {
    if (blockIdx.x < KNB) {
        // ---- key normalize (double-float fp32) ----
        int row = blockIdx.x * 8 + (threadIdx.x >> 5);
        int lane = threadIdx.x & 31;
        const float4* s4 = (const float4*)(keys + (size_t)row * DKEY);
        float4 a = s4[lane], b = s4[lane + 32];
        float v[8] = {a.x, a.y, a.z, a.w, b.x, b.y, b.z, b.w};

        float s = 0.f, c = 0.f;
        #pragma unroll
        for (int i = 0; i < 8; i++) {
            float p = __fmul_rn(v[i], v[i]);
            float e = __fmaf_rn(v[i], v[i], -p);
            float t  = __fadd_rn(s, p);
            float bv = __fadd_rn(t, -s);
            float err = __fadd_rn(__fadd_rn(s, -__fadd_rn(t, -bv)), __fadd_rn(p, -bv));
            s = t;
            c = __fadd_rn(c, __fadd_rn(err, e));
        }
        double d = (double)s + (double)c;
        #pragma unroll
        for (int o = 16; o; o >>= 1) d += __shfl_xor_sync(0xffffffffu, d, o);
        double inv = 1.0 / fmax(sqrt(d), 1e-12);
        float ih = (float)inv;
        float il = (float)(inv - (double)ih);

        float h2[8], l2[8];
        #pragma unroll
        for (int i = 0; i < 8; i++) {
            float p = __fmul_rn(v[i], ih);
            float e = __fmaf_rn(v[i], ih, -p);
            float lo = __fmaf_rn(v[i], il, e);
            float hh = __fadd_rn(p, lo);
            h2[i] = hh;
            l2[i] = __fadd_rn(lo, -__fadd_rn(hh, -p));
        }
        float4* dh = (float4*)(g_kn_hi + (size_t)row * DKEY);
        float4* dl = (float4*)(g_kn_lo + (size_t)row * DKEY);
        dh[lane]      = make_float4(h2[0], h2[1], h2[2], h2[3]);
        dh[lane + 32] = make_float4(h2[4], h2[5], h2[6], h2[7]);
        dl[lane]      = make_float4(l2[0], l2[1], l2[2], l2[3]);
        dl[lane + 32] = make_float4(l2[4], l2[5], l2[6], l2[7]);
        __nv_bfloat162* db = (__nv_bfloat162*)(g_kb + (size_t)row * DKEY);
        db[lane*2 + 0]  = __nv_bfloat162(__float2bfloat16(h2[0]), __float2bfloat16(h2[1]));
        db[lane*2 + 1]  = __nv_bfloat162(__float2bfloat16(h2[2]), __float2bfloat16(h2[3]));
        db[64 + lane*2 + 0] = __nv_bfloat162(__float2bfloat16(h2[4]), __float2bfloat16(h2[5]));
        db[64 + lane*2 + 1] = __nv_bfloat162(__float2bfloat16(h2[6]), __float2bfloat16(h2[7]));
        return;
    }
    if (blockIdx.x < KNB + NXB) {
        int i = (blockIdx.x - KNB) * 256 + threadIdx.x;
        float v = x[i];
        bf16 h = __float2bfloat16(v);
        g_xhi[i] = h;
        g_xlo[i] = __float2bfloat16(__fadd_rn(v, -__bfloat162float(h)));
        return;
    }
    {
        int i = (blockIdx.x - KNB - NXB) * 256 + threadIdx.x;
        const float* src; bf16 *hi, *lo; int j;
        if (i < NWG) { src = wg; hi = g_wghi; lo = g_wglo; j = i; }
        else { src = wo; hi = g_wohi; lo = g_wolo; j = i - NWG; }
        float v = src[j];
        bf16 h = __float2bfloat16(v);
        hi[j] = h;
        lo[j] = __float2bfloat16(__fadd_rn(v, -__bfloat162float(h)));
    }
}

// ------------------------------ exact q GEMM v2: 32x32 tile, 1024 blocks, offset-accumulator ------------------------------
#define QTM 32
#define QTN 32
#define QTK 32
#define QOFF 1024.0f

__global__ __launch_bounds__(256) void qexact_kernel(const float* __restrict__ x,
                                                     const float* __restrict__ wq) {
    __shared__ float sX[QTK][QTM + 4];
    __shared__ float sW[QTK][QTN + 4];
    int bt = blockIdx.y * QTM;
    int bq = blockIdx.x * QTN;
    int tid = threadIdx.x;
    int ty = tid >> 4;
    int tx = tid & 15;

    float A[2][2], A2[2][2];
    #pragma unroll
    for (int i = 0; i < 2; i++)
        #pragma unroll
        for (int j = 0; j < 2; j++) { A[i][j] = QOFF; A2[i][j] = 0.f; }

    int lrow = tid >> 3;
    int lc4 = (tid & 7) * 4;

    for (int kc = 0; kc < DMODEL; kc += QTK) {
        float4 v = *(const float4*)(x + (size_t)(bt + lrow) * DMODEL + kc + lc4);
        sX[lc4+0][lrow] = v.x; sX[lc4+1][lrow] = v.y;
        sX[lc4+2][lrow] = v.z; sX[lc4+3][lrow] = v.w;
        float4 w = *(const float4*)(wq + (size_t)(bq + lrow) * DMODEL + kc + lc4);
        sW[lc4+0][lrow] = w.x; sW[lc4+1][lrow] = w.y;
        sW[lc4+2][lrow] = w.z; sW[lc4+3][lrow] = w.w;
        __syncthreads();
        #pragma unroll 8
        for (int k = 0; k < QTK; k++) {
            float2 rx = *(const float2*)&sX[k][ty * 2];
            float2 rw = *(const float2*)&sW[k][tx * 2];
            float ax[2] = {rx.x, rx.y};
            float bw[2] = {rw.x, rw.y};
            #pragma unroll
            for (int i = 0; i < 2; i++)
                #pragma unroll
                for (int j = 0; j < 2; j++) {
                    float p = __fmul_rn(ax[i], bw[j]);
                    float e = __fmaf_rn(ax[i], bw[j], -p);
                    float t = __fadd_rn(A[i][j], p);
                    float z = __fadd_rn(t, -A[i][j]);
                    float r = __fadd_rn(p, -z);
                    A[i][j] = t;
                    A2[i][j] = __fadd_rn(A2[i][j], __fadd_rn(r, e));
                }
        }
        __syncthreads();
    }

    #pragma unroll
    for (int i = 0; i < 2; i++)
        #pragma unroll
        for (int j = 0; j < 2; j++) {
            double sum = (double)__fadd_rn(A[i][j], -QOFF) + (double)A2[i][j];
            float hi = (float)sum;
            float lo = (float)(sum - (double)hi);
            g_q2[(size_t)(bt + ty*2 + i) * DKEY + (bq + tx*2 + j)] = make_float2(hi, lo);
        }
}

// ------------------------------ q normalize (fp64, ILP) ------------------------------
__global__ void qnorm_kernel() {
    int row = blockIdx.x * 8 + (threadIdx.x >> 5);
    int lane = threadIdx.x & 31;
    const float2* q = g_q2 + (size_t)row * DKEY;
    double v[8];
    double s0 = 0.0, s1 = 0.0, s2 = 0.0, s3 = 0.0;
    #pragma unroll
    for (int i = 0; i < 8; i += 4) {
        float2 p0 = q[lane + i * 32];
        float2 p1 = q[lane + (i+1) * 32];
        float2 p2 = q[lane + (i+2) * 32];
        float2 p3 = q[lane + (i+3) * 32];
        v[i]   = (double)p0.x + (double)p0.y;
        v[i+1] = (double)p1.x + (double)p1.y;
        v[i+2] = (double)p2.x + (double)p2.y;
        v[i+3] = (double)p3.x + (double)p3.y;
        s0 = fma(v[i], v[i], s0);
        s1 = fma(v[i+1], v[i+1], s1);
        s2 = fma(v[i+2], v[i+2], s2);
        s3 = fma(v[i+3], v[i+3], s3);
    }
    double ss = (s0 + s1) + (s2 + s3);
    #pragma unroll
    for (int o = 16; o; o >>= 1) ss += __shfl_xor_sync(0xffffffffu, ss, o);
    double inv = 1.0 / fmax(sqrt(ss), 1e-12);
    #pragma unroll
    for (int i = 0; i < 8; i++) {
        double qn = v[i] * inv;
        float hi = (float)qn;
        float lo = (float)(qn - (double)hi);
        size_t gi = (size_t)row * DKEY + lane + i * 32;
        g_qn_hi[gi] = hi;
        g_qn_lo[gi] = lo;
        g_qb[gi] = __float2bfloat16(hi);
    }
}

// ------------------------------ sims GEMM v1 (proven): full-K in smem, 128x256 tile + chunk maxima ------------------------------
#define SBM 128
#define SBN 256
#define SPAD 264
#define SIMS_SMEM ((SBM * SPAD + SBN * SPAD) * 2)

__global__ __launch_bounds__(256, 1) void sims_kernel() {
    extern __shared__ char smem_raw[];
    bf16* sQ = (bf16*)smem_raw;
    bf16* sK = sQ + SBM * SPAD;
    float* stagef = (float*)sK;

    int bm = blockIdx.y * SBM;
    int bn = blockIdx.x * SBN;
    int tid = threadIdx.x;
    int warp = tid >> 5;
    int wr = warp >> 2;
    int wc = warp & 3;

    #pragma unroll
    for (int rep = 0; rep < 16; rep++) {
        int idx = tid + rep * 256;
        int row = idx >> 5, g = idx & 31;
        *(float4*)(sQ + row * SPAD + g * 8) =
            *(const float4*)(g_qb + (size_t)(bm + row) * DKEY + g * 8);
    }
    #pragma unroll
    for (int rep = 0; rep < 32; rep++) {
        int idx = tid + rep * 256;
        int row = idx >> 5, g = idx & 31;
        *(float4*)(sK + row * SPAD + g * 8) =
            *(const float4*)(g_kb + (size_t)(bn + row) * DKEY + g * 8);
    }
    __syncthreads();

    wmma::fragment<wmma::accumulator, 16, 16, 16, float> acc[4][4];
    #pragma unroll
    for (int i = 0; i < 4; i++)
        #pragma unroll
        for (int j = 0; j < 4; j++) wmma::fill_fragment(acc[i][j], 0.0f);

    #pragma unroll
    for (int ks = 0; ks < DKEY / 16; ks++) {
        int kc = ks * 16;
        wmma::fragment<wmma::matrix_a, 16, 16, 16, bf16, wmma::row_major> a[4];
        wmma::fragment<wmma::matrix_b, 16, 16, 16, bf16, wmma::col_major> b[4];
        #pragma unroll
        for (int i = 0; i < 4; i++)
            wmma::load_matrix_sync(a[i], sQ + (wr * 64 + i * 16) * SPAD + kc, SPAD);
        #pragma unroll
        for (int j = 0; j < 4; j++)
            wmma::load_matrix_sync(b[j], sK + (wc * 64 + j * 16) * SPAD + kc, SPAD);
        #pragma unroll
        for (int i = 0; i < 4; i++)
            #pragma unroll
            for (int j = 0; j < 4; j++)
                wmma::mma_sync(acc[i][j], a[i], b[j], acc[i][j]);
    }
    __syncthreads();

    #pragma unroll
    for (int i = 0; i < 4; i++)
        #pragma unroll
        for (int j = 0; j < 4; j++)
            wmma::store_matrix_sync(stagef + (wr * 64 + i * 16) * 260 + wc * 64 + j * 16,
                                    acc[i][j], 260, wmma::mem_row_major);
    __syncthreads();

    #pragma unroll
    for (int rep = 0; rep < 16; rep++) {
        int idx = tid + rep * 256;
        int row = idx >> 5, g = idx & 31;
        const float* src = stagef + row * 260 + g * 8;
        float4 f0 = *(const float4*)src;
        float4 f1 = *(const float4*)(src + 4);
        __align__(16) bf16 tmp[8];
        tmp[0] = __float2bfloat16(f0.x); tmp[1] = __float2bfloat16(f0.y);
        tmp[2] = __float2bfloat16(f0.z); tmp[3] = __float2bfloat16(f0.w);
        tmp[4] = __float2bfloat16(f1.x); tmp[5] = __float2bfloat16(f1.y);
        tmp[6] = __float2bfloat16(f1.z); tmp[7] = __float2bfloat16(f1.w);
        *(float4*)(g_sims + (size_t)(bm + row) * NMEM + bn + g * 8) = *(float4*)tmp;

        float mx = __bfloat162float(tmp[0]);
        #pragma unroll
        for (int e = 1; e < 8; e++) mx = fmaxf(mx, __bfloat162float(tmp[e]));
        #pragma unroll
        for (int off = 1; off < 8; off <<= 1)
            mx = fmaxf(mx, __shfl_xor_sync(0xffffffffu, mx, off));
        if ((g & 7) == 0)
            g_blkmax[(size_t)(bm + row) * NCHUNK + (bn >> 6) + (g >> 3)] = __float2bfloat16(mx);
    }
}

// ------------------------------ top-64 preselect v3: chunk-max pruning, small smem ------------------------------
__device__ __forceinline__ unsigned ordkey16(unsigned u) {
    return (u & 0x8000u) ? (u ^ 0xFFFFu) : (u | 0x8000u);
}

__global__ __launch_bounds__(256) void topk_kernel() {
    int t = blockIdx.x;
    extern __shared__ unsigned short sbuf[];        // TKCAP ordkeys = 16 KB
    __shared__ unsigned short sclist[NCHUNK];
    __shared__ unsigned hist[256];
    __shared__ unsigned sh_b, sh_above, sh_KM, sh_nsel, sh_thr, sh_K1, ctrG, ctrE;
    int tid = threadIdx.x;

    hist[tid] = 0;
    __syncthreads();
    unsigned mk0, mk1;
    {
        const unsigned short* bm = (const unsigned short*)(g_blkmax + (size_t)t * NCHUNK);
        mk0 = ordkey16((unsigned)bm[tid]);
        mk1 = ordkey16((unsigned)bm[tid + 256]);
        atomicAdd(&hist[mk0 >> 8], 1u);
        atomicAdd(&hist[mk1 >> 8], 1u);
    }
    __syncthreads();
    if (tid == 0) {
        unsigned cum = 0; int b = 255;
        for (; b > 0; b--) { if (cum + hist[b] >= NCAND) break; cum += hist[b]; }
        sh_b = (unsigned)b; sh_above = cum;
    }
    __syncthreads();
    unsigned b = sh_b;
    hist[tid] = 0;
    __syncthreads();
    if ((mk0 >> 8) == b) atomicAdd(&hist[mk0 & 255u], 1u);
    if ((mk1 >> 8) == b) atomicAdd(&hist[mk1 & 255u], 1u);
    __syncthreads();
    if (tid == 0) {
        unsigned cum = sh_above; int l = 255;
        for (; l > 0; l--) { if (cum + hist[l] >= NCAND) break; cum += hist[l]; }
        sh_KM = (b << 8) | (unsigned)l;
        sh_nsel = 0;
    }
    __syncthreads();

    unsigned KM = sh_KM;
    if (mk0 >= KM) { unsigned p = atomicAdd(&sh_nsel, 1u); sclist[p] = (unsigned short)tid; }
    if (mk1 >= KM) { unsigned p = atomicAdd(&sh_nsel, 1u); sclist[p] = (unsigned short)(tid + 256); }
    __syncthreads();
    int ns = (int)sh_nsel * 64;

    hist[tid] = 0;
    __syncthreads();
    const unsigned short* row = (const unsigned short*)(g_sims + (size_t)t * NMEM);
    for (int j = tid; j < ns; j += 256) {
        int chunk = sclist[j >> 6];
        unsigned k = ordkey16((unsigned)row[chunk * 64 + (j & 63)]);
        if (j < TKCAP) sbuf[j] = (unsigned short)k;
        atomicAdd(&hist[k >> 8], 1u);
    }
    __syncthreads();
    if (tid == 0) {
        unsigned cum = 0; int bb = 255;
        for (; bb > 0; bb--) { if (cum + hist[bb] >= NCAND) break; cum += hist[bb]; }
        sh_b = (unsigned)bb; sh_above = cum;
    }
    __syncthreads();
    unsigned b2 = sh_b;
    hist[tid] = 0;
    __syncthreads();
    for (int j = tid; j < ns; j += 256) {
        unsigned k = (j < TKCAP) ? (unsigned)sbuf[j]
                   : ordkey16((unsigned)row[sclist[j >> 6] * 64 + (j & 63)]);
        if ((k >> 8) == b2) atomicAdd(&hist[k & 255u], 1u);
    }
    __syncthreads();
    if (tid == 0) {
        unsigned cum = sh_above; int l = 255;
        for (; l > 0; l--) { if (cum + hist[l] >= NCAND) break; cum += hist[l]; }
        sh_thr = (b2 << 8) | (unsigned)l;
        sh_K1 = cum;
        ctrG = 0; ctrE = 0;
    }
    __syncthreads();

    unsigned thr = sh_thr, K1 = sh_K1;
    for (int j = tid; j < ns; j += 256) {
        unsigned k = (j < TKCAP) ? (unsigned)sbuf[j]
                   : ordkey16((unsigned)row[sclist[j >> 6] * 64 + (j & 63)]);
        if (k > thr) {
            unsigned p = atomicAdd(&ctrG, 1u);
            g_cand[t * NCAND + p] = (int)sclist[j >> 6] * 64 + (j & 63);
        } else if (k == thr) {
            unsigned p = atomicAdd(&ctrE, 1u);
            if (K1 + p < NCAND) g_cand[t * NCAND + K1 + p] = (int)sclist[j >> 6] * 64 + (j & 63);
        }
    }
}

// ------------------------------ exact double-float rescore + top-32 + softmax ------------------------------
__device__ __forceinline__ void kmac(float a, float b, float& s, float& c) {
    float p  = __fmul_rn(a, b);
    float e  = __fmaf_rn(a, b, -p);
    float t  = __fadd_rn(s, p);
    float bv = __fadd_rn(t, -s);
    float e1 = __fadd_rn(s, -__fadd_rn(t, -bv));
    float e2 = __fadd_rn(p, -bv);
    s = t;
    c = __fadd_rn(c, __fadd_rn(e, __fadd_rn(e1, e2)));
}

__global__ __launch_bounds__(256) void rescore_kernel() {
    int t = blockIdx.x;
    int tid = threadIdx.x;
    __shared__ __align__(16) float qhi[DKEY];
    __shared__ __align__(16) float qlo[DKEY];
    __shared__ float cval[NCAND];
    __shared__ int cidx[NCAND];
    __shared__ float sval[TOPK];
    __shared__ int sidx[TOPK];

    qhi[tid] = g_qn_hi[(size_t)t * DKEY + tid];
    qlo[tid] = g_qn_lo[(size_t)t * DKEY + tid];
    if (tid < NCAND) cidx[tid] = g_cand[t * NCAND + tid];
    __syncthreads();

    int c = tid >> 2, part = tid & 3;
    int ki = cidx[c];
    const float* khi = g_kn_hi + (size_t)ki * DKEY + part * 64;
    const float* klo = g_kn_lo + (size_t)ki * DKEY + part * 64;
    const float* qh = qhi + part * 64;
    const float* ql = qlo + part * 64;

    float s = 0.f, comp = 0.f, cr = 0.f;
    #pragma unroll 8
    for (int i = 0; i < 64; i++) {
        float kh = khi[i], kl = klo[i];
        float qhv = qh[i], qlv = ql[i];
        kmac(qhv, kh, s, comp);
        cr = __fmaf_rn(qhv, kl, cr);
        cr = __fmaf_rn(qlv, kh, cr);
    }
    double v = (double)s + (double)comp + (double)cr;
    v += __shfl_xor_sync(0xffffffffu, v, 1);
    v += __shfl_xor_sync(0xffffffffu, v, 2);
    if (part == 0) cval[c] = (float)v;
    __syncthreads();

    if (tid < NCAND) {
        float val = cval[tid]; int myi = cidx[tid];
        int rnk = 0;
        #pragma unroll 8
        for (int j = 0; j < NCAND; j++) {
            float u = cval[j];
            rnk += (u > val) || (u == val && cidx[j] < myi);
        }
        if (rnk < TOPK) { sval[rnk] = val; sidx[rnk] = myi; }
    }
    __syncthreads();

    if (tid < 32) {
        float val = sval[tid];
        float m = val;
        #pragma unroll
        for (int o = 16; o; o >>= 1) m = fmaxf(m, __shfl_xor_sync(0xffffffffu, m, o));
        float e = expf(val - m);
        float sum = e;
        #pragma unroll
        for (int o = 16; o; o >>= 1) sum += __shfl_xor_sync(0xffffffffu, sum, o);
        g_w[t * TOPK + tid] = e / sum;
        g_widx[t * TOPK + tid] = sidx[tid];
    }
}

// ------------------------------ weighted values gather ------------------------------
__global__ void gather_kernel(const float* __restrict__ values) {
    int t = blockIdx.x, tid = threadIdx.x;
    __shared__ float w[TOPK];
    __shared__ int idx[TOPK];
    if (tid < TOPK) { w[tid] = g_w[t * TOPK + tid]; idx[tid] = g_widx[t * TOPK + tid]; }
    __syncthreads();
    float4 acc = make_float4(0.f, 0.f, 0.f, 0.f);
    #pragma unroll 8
    for (int i = 0; i < TOPK; i++) {
        const float4 v = *((const float4*)(values + (size_t)idx[i] * DVAL) + tid);
        float wi = w[i];
        acc.x = fmaf(wi, v.x, acc.x);
        acc.y = fmaf(wi, v.y, acc.y);
        acc.z = fmaf(wi, v.z, acc.z);
        acc.w = fmaf(wi, v.w, acc.w);
    }
    ((float4*)(g_memout + (size_t)t * DVAL))[tid] = acc;
}

// ------------------------------ 3-term split-bf16 GEMM, double-buffered ------------------------------
template<int WHICH>
__global__ __launch_bounds__(256) void gemm_kernel(float* __restrict__ Cout) {
    constexpr int N = (WHICH == 1) ? DVAL : DMODEL;
    constexpr int K = (WHICH == 2) ? DVAL : DMODEL;
    constexpr int BM = 128, BN = 64, KC = 16;
    constexpr int NIT = K / KC;

    const bf16* Ahi = (WHICH == 2) ? g_hhi : g_xhi;
    const bf16* Alo = (WHICH == 2) ? g_hlo : g_xlo;
    const bf16* Bhi = (WHICH == 1) ? g_wghi : g_wohi;
    const bf16* Blo = (WHICH == 1) ? g_wglo : g_wolo;

    extern __shared__ char smem_raw[];
    bf16* sbuf = (bf16*)smem_raw;
    float* stage = (float*)smem_raw;

    int bm = blockIdx.y * BM;
    int bn = blockIdx.x * BN;
    int tid = threadIdx.x;
    int warp = tid >> 5;
    int wr = warp >> 1;
    int wc = warp & 1;

    wmma::fragment<wmma::accumulator, 16, 16, 16, float> acc[2][2];
    #pragma unroll
    for (int i = 0; i < 2; i++)
        #pragma unroll
        for (int j = 0; j < 2; j++) wmma::fill_fragment(acc[i][j], 0.0f);

    int ar = tid >> 1, ah = (tid & 1) * 8;
    int br = tid >> 2, bh2 = (tid & 3);

    const int OAH = 0, OAL = 2048, OBH = 4096, OBL = 5120;

    {
        const float4 va = *(const float4*)(Ahi + (size_t)(bm + ar) * K + ah);
        const float4 vb = *(const float4*)(Alo + (size_t)(bm + ar) * K + ah);
        *(float4*)(sbuf + OAH + ar * KC + ah) = va;
        *(float4*)(sbuf + OAL + ar * KC + ah) = vb;
        const bf16* bsrc = (bh2 & 2) ? Blo : Bhi;
        int bofs = (bh2 & 1) * 8;
        const float4 vc = *(const float4*)(bsrc + (size_t)(bn + br) * K + bofs);
        *(float4*)(sbuf + ((bh2 & 2) ? OBL : OBH) + br * KC + bofs) = vc;
    }
    __syncthreads();

    #pragma unroll 4
    for (int it = 0; it < NIT; it++) {
        int cur = (it & 1) * 6144;
        float4 pa, pal, pb;
        if (it + 1 < NIT) {
            int kc = (it + 1) * KC;
            pa  = *(const float4*)(Ahi + (size_t)(bm + ar) * K + kc + ah);
            pal = *(const float4*)(Alo + (size_t)(bm + ar) * K + kc + ah);
            const bf16* bsrc = (bh2 & 2) ? Blo : Bhi;
            pb  = *(const float4*)(bsrc + (size_t)(bn + br) * K + kc + (bh2 & 1) * 8);
        }

        wmma::fragment<wmma::matrix_a, 16, 16, 16, bf16, wmma::row_major> a0, a1, c0, c1;
        wmma::fragment<wmma::matrix_b, 16, 16, 16, bf16, wmma::col_major> b0, b1;

        wmma::load_matrix_sync(a0, sbuf + cur + OAH + (wr * 32 + 0) * KC, KC);
        wmma::load_matrix_sync(a1, sbuf + cur + OAH + (wr * 32 + 16) * KC, KC);
        wmma::load_matrix_sync(b0, sbuf + cur + OBH + (wc * 32 + 0) * KC, KC);
        wmma::load_matrix_sync(b1, sbuf + cur + OBH + (wc * 32 + 16) * KC, KC);
        wmma::mma_sync(acc[0][0], a0, b0, acc[0][0]);
        wmma::mma_sync(acc[0][1], a0, b1, acc[0][1]);
        wmma::mma_sync(acc[1][0], a1, b0, acc[1][0]);
        wmma::mma_sync(acc[1][1], a1, b1, acc[1][1]);

        wmma::load_matrix_sync(c0, sbuf + cur + OAL + (wr * 32 + 0) * KC, KC);
        wmma::load_matrix_sync(c1, sbuf + cur + OAL + (wr * 32 + 16) * KC, KC);
        wmma::mma_sync(acc[0][0], c0, b0, acc[0][0]);
        wmma::mma_sync(acc[0][1], c0, b1, acc[0][1]);
        wmma::mma_sync(acc[1][0], c1, b0, acc[1][0]);
        wmma::mma_sync(acc[1][1], c1, b1, acc[1][1]);

        wmma::load_matrix_sync(b0, sbuf + cur + OBL + (wc * 32 + 0) * KC, KC);
        wmma::load_matrix_sync(b1, sbuf + cur + OBL + (wc * 32 + 16) * KC, KC);
        wmma::mma_sync(acc[0][0], a0, b0, acc[0][0]);
        wmma::mma_sync(acc[0][1], a0, b1, acc[0][1]);
        wmma::mma_sync(acc[1][0], a1, b0, acc[1][0]);
        wmma::mma_sync(acc[1][1], a1, b1, acc[1][1]);

        if (it + 1 < NIT) {
            int nxt = ((it + 1) & 1) * 6144;
            *(float4*)(sbuf + nxt + OAH + ar * KC + ah) = pa;
            *(float4*)(sbuf + nxt + OAL + ar * KC + ah) = pal;
            *(float4*)(sbuf + nxt + ((bh2 & 2) ? OBL : OBH) + br * KC + (bh2 & 1) * 8) = pb;
            __syncthreads();
        }
    }

    if (WHICH == 2) {
        #pragma unroll
        for (int i = 0; i < 2; i++)
            #pragma unroll
            for (int j = 0; j < 2; j++)
                wmma::store_matrix_sync(Cout + (size_t)(bm + wr * 32 + i * 16) * N + bn + wc * 32 + j * 16,
                                        acc[i][j], N, wmma::mem_row_major);
    } else {
        __syncthreads();
        #pragma unroll
        for (int i = 0; i < 2; i++)
            #pragma unroll
            for (int j = 0; j < 2; j++)
                wmma::store_matrix_sync(stage + (wr * 32 + i * 16) * 68 + wc * 32 + j * 16,
                                        acc[i][j], 68, wmma::mem_row_major);
        __syncthreads();
        for (int e = tid; e < BM * BN; e += 256) {
            int lr = e >> 6, lc = e & 63;
            float gpre = stage[lr * 68 + lc];
            float sg = gpre / (1.0f + expf(-gpre));
            size_t gi = (size_t)(bm + lr) * N + bn + lc;
            float h = sg * g_memout[gi];
            bf16 hh = __float2bfloat16(h);
            g_hhi[gi] = hh;
            g_hlo[gi] = __float2bfloat16(h - __bfloat162float(hh));
        }
    }
}

// ------------------------------ launcher ------------------------------
extern "C" void kernel_launch(void* const* d_in, const int* in_sizes, int n_in,
                              void* d_out, int out_size) {
    const float *x = nullptr, *keys = nullptr, *values = nullptr,
                *w_q = nullptr, *w_gate = nullptr, *w_out = nullptr;
    for (int i = 0; i < n_in; i++) {
        int sz = in_sizes[i];
        const float* p = (const float*)d_in[i];
        if (sz == BS_TOK * DMODEL)      x = p;
        else if (sz == NMEM * DKEY)     keys = p;
        else if (sz == NMEM * DVAL)     values = p;
        else if (sz == DKEY * DMODEL)   w_q = p;
        else if (sz == DVAL * DMODEL) { if (!w_gate) w_gate = p; else w_out = p; }
    }
    float* out = (float*)d_out;

    cudaFuncSetAttribute(sims_kernel, cudaFuncAttributeMaxDynamicSharedMemorySize, SIMS_SMEM);

    size_t smem_g2 = 2 * 6144 * sizeof(bf16);                            // 24576 B
    size_t smem_g1 = (size_t)128 * 68 * sizeof(float);                   // 34816 B
    size_t smem_tk = TKCAP * 2;                                          // 16384 B

    // launch order: #4 = sims v1 (profiled; stall data for tcgen05 decision)
    prep_kernel<<<KNB + NXB + NWB, 256>>>(keys, x, w_gate, w_out);           // 1 (knorm+splitx+splitw)
    qexact_kernel<<<dim3(DKEY / QTN, BS_TOK / QTM), 256>>>(x, w_q);          // 2
    qnorm_kernel<<<BS_TOK / 8, 256>>>();                                     // 3
    sims_kernel<<<dim3(NMEM / SBN, BS_TOK / SBM), 256, SIMS_SMEM>>>();       // 4 <- profiled
    topk_kernel<<<BS_TOK, 256, smem_tk>>>();                                 // 5
    rescore_kernel<<<BS_TOK, 256>>>();                                       // 6
    gather_kernel<<<BS_TOK, 256>>>(values);                                  // 7
    gemm_kernel<1><<<dim3(DVAL / 64, BS_TOK / 128), 256, smem_g1>>>(nullptr);// 8
    gemm_kernel<2><<<dim3(DMODEL / 64, BS_TOK / 128), 256, smem_g2>>>(out);  // 9
}

// round 14
// speedup vs baseline: 1.0499x; 1.0381x over previous
#include <cuda_runtime.h>
#include <cuda_bf16.h>
#include <mma.h>

using namespace nvcuda;

typedef __nv_bfloat16 bf16;

#define BS_TOK 4096
#define DMODEL 1024
#define NMEM   32768
#define DKEY   256
#define DVAL   1024
#define TOPK   32
#define NCAND  64
#define NCHUNK 512
#define TKCAP  8192

// ------------------------------ scratch (device globals) ------------------------------
__device__ __align__(16) float2 g_q2[BS_TOK * DKEY];
__device__ __align__(16) float  g_qn_hi[BS_TOK * DKEY];
__device__ __align__(16) float  g_qn_lo[BS_TOK * DKEY];
__device__ __align__(16) bf16   g_qb[BS_TOK * DKEY];
__device__ __align__(16) float  g_kn_hi[NMEM * DKEY];
__device__ __align__(16) float  g_kn_lo[NMEM * DKEY];
__device__ __align__(16) bf16   g_kb[NMEM * DKEY];
__device__ __align__(16) bf16   g_sims[(size_t)BS_TOK * NMEM];   // 256 MB
__device__ __align__(16) bf16   g_blkmax[BS_TOK * NCHUNK];       // 4 MB chunk maxima
__device__ int   g_cand[BS_TOK * NCAND];
__device__ __align__(16) float g_memout[BS_TOK * DVAL];
__device__ __align__(16) bf16 g_xhi[BS_TOK * DMODEL];
__device__ __align__(16) bf16 g_xlo[BS_TOK * DMODEL];
__device__ __align__(16) bf16 g_wghi[DVAL * DMODEL];
__device__ __align__(16) bf16 g_wglo[DVAL * DMODEL];
__device__ __align__(16) bf16 g_wohi[DMODEL * DVAL];
__device__ __align__(16) bf16 g_wolo[DMODEL * DVAL];
__device__ __align__(16) bf16 g_hhi[BS_TOK * DVAL];
__device__ __align__(16) bf16 g_hlo[BS_TOK * DVAL];

// ------------------------------ split x / weights -> bf16 hi/lo ------------------------------
#define NX (BS_TOK * DMODEL)
#define NWG (DVAL * DMODEL)
#define NWO (DMODEL * DVAL)

__global__ void splitx_kernel(const float* __restrict__ x) {
    int i = blockIdx.x * blockDim.x + threadIdx.x;
    if (i >= NX) return;
    float v = x[i];
    bf16 h = __float2bfloat16(v);
    g_xhi[i] = h;
    g_xlo[i] = __float2bfloat16(__fadd_rn(v, -__bfloat162float(h)));
}

__global__ void splitw_kernel(const float* __restrict__ wg,
                              const float* __restrict__ wo) {
    int i = blockIdx.x * blockDim.x + threadIdx.x;
    const float* src; bf16 *hi, *lo; int j;
    if (i < NWG) { src = wg; hi = g_wghi; lo = g_wglo; j = i; }
    else if (i < NWG + NWO) { src = wo; hi = g_wohi; lo = g_wolo; j = i - NWG; }
    else return;
    float v = src[j];
    bf16 h = __float2bfloat16(v);
    hi[j] = h;
    lo[j] = __float2bfloat16(__fadd_rn(v, -__bfloat162float(h)));
}

// ------------------------------ key normalize (double-float fp32) ------------------------------
__global__ __launch_bounds__(256) void knorm_kernel(const float* __restrict__ keys) {
    int row = blockIdx.x * 8 + (threadIdx.x >> 5);
    int lane = threadIdx.x & 31;
    const float4* s4 = (const float4*)(keys + (size_t)row * DKEY);
    float4 a = s4[lane], b = s4[lane + 32];
    float v[8] = {a.x, a.y, a.z, a.w, b.x, b.y, b.z, b.w};

    float s = 0.f, c = 0.f;
    #pragma unroll
    for (int i = 0; i < 8; i++) {
        float p = __fmul_rn(v[i], v[i]);
        float e = __fmaf_rn(v[i], v[i], -p);
        float t  = __fadd_rn(s, p);
        float bv = __fadd_rn(t, -s);
        float err = __fadd_rn(__fadd_rn(s, -__fadd_rn(t, -bv)), __fadd_rn(p, -bv));
        s = t;
        c = __fadd_rn(c, __fadd_rn(err, e));
    }
    double d = (double)s + (double)c;
    #pragma unroll
    for (int o = 16; o; o >>= 1) d += __shfl_xor_sync(0xffffffffu, d, o);
    double inv = 1.0 / fmax(sqrt(d), 1e-12);
    float ih = (float)inv;
    float il = (float)(inv - (double)ih);

    float h2[8], l2[8];
    #pragma unroll
    for (int i = 0; i < 8; i++) {
        float p = __fmul_rn(v[i], ih);
        float e = __fmaf_rn(v[i], ih, -p);
        float lo = __fmaf_rn(v[i], il, e);
        float hh = __fadd_rn(p, lo);
        h2[i] = hh;
        l2[i] = __fadd_rn(lo, -__fadd_rn(hh, -p));
    }
    float4* dh = (float4*)(g_kn_hi + (size_t)row * DKEY);
    float4* dl = (float4*)(g_kn_lo + (size_t)row * DKEY);
    dh[lane]      = make_float4(h2[0], h2[1], h2[2], h2[3]);
    dh[lane + 32] = make_float4(h2[4], h2[5], h2[6], h2[7]);
    dl[lane]      = make_float4(l2[0], l2[1], l2[2], l2[3]);
    dl[lane + 32] = make_float4(l2[4], l2[5], l2[6], l2[7]);
    __nv_bfloat162* db = (__nv_bfloat162*)(g_kb + (size_t)row * DKEY);
    db[lane*2 + 0]  = __nv_bfloat162(__float2bfloat16(h2[0]), __float2bfloat16(h2[1]));
    db[lane*2 + 1]  = __nv_bfloat162(__float2bfloat16(h2[2]), __float2bfloat16(h2[3]));
    db[64 + lane*2 + 0] = __nv_bfloat162(__float2bfloat16(h2[4]), __float2bfloat16(h2[5]));
    db[64 + lane*2 + 1] = __nv_bfloat162(__float2bfloat16(h2[6]), __float2bfloat16(h2[7]));
}

// ------------------------------ exact q GEMM v2: 32x32 tile, 1024 blocks, offset-accumulator ------------------------------
#define QTM 32
#define QTN 32
#define QTK 32
#define QOFF 1024.0f

__global__ __launch_bounds__(256) void qexact_kernel(const float* __restrict__ x,
                                                     const float* __restrict__ wq) {
    __shared__ float sX[QTK][QTM + 4];
    __shared__ float sW[QTK][QTN + 4];
    int bt = blockIdx.y * QTM;
    int bq = blockIdx.x * QTN;
    int tid = threadIdx.x;
    int ty = tid >> 4;
    int tx = tid & 15;

    float A[2][2], A2[2][2];
    #pragma unroll
    for (int i = 0; i < 2; i++)
        #pragma unroll
        for (int j = 0; j < 2; j++) { A[i][j] = QOFF; A2[i][j] = 0.f; }

    int lrow = tid >> 3;
    int lc4 = (tid & 7) * 4;

    for (int kc = 0; kc < DMODEL; kc += QTK) {
        float4 v = *(const float4*)(x + (size_t)(bt + lrow) * DMODEL + kc + lc4);
        sX[lc4+0][lrow] = v.x; sX[lc4+1][lrow] = v.y;
        sX[lc4+2][lrow] = v.z; sX[lc4+3][lrow] = v.w;
        float4 w = *(const float4*)(wq + (size_t)(bq + lrow) * DMODEL + kc + lc4);
        sW[lc4+0][lrow] = w.x; sW[lc4+1][lrow] = w.y;
        sW[lc4+2][lrow] = w.z; sW[lc4+3][lrow] = w.w;
        __syncthreads();
        #pragma unroll 8
        for (int k = 0; k < QTK; k++) {
            float2 rx = *(const float2*)&sX[k][ty * 2];
            float2 rw = *(const float2*)&sW[k][tx * 2];
            float ax[2] = {rx.x, rx.y};
            float bw[2] = {rw.x, rw.y};
            #pragma unroll
            for (int i = 0; i < 2; i++)
                #pragma unroll
                for (int j = 0; j < 2; j++) {
                    float p = __fmul_rn(ax[i], bw[j]);
                    float e = __fmaf_rn(ax[i], bw[j], -p);
                    float t = __fadd_rn(A[i][j], p);
                    float z = __fadd_rn(t, -A[i][j]);
                    float r = __fadd_rn(p, -z);
                    A[i][j] = t;
                    A2[i][j] = __fadd_rn(A2[i][j], __fadd_rn(r, e));
                }
        }
        __syncthreads();
    }

    #pragma unroll
    for (int i = 0; i < 2; i++)
        #pragma unroll
        for (int j = 0; j < 2; j++) {
            double sum = (double)__fadd_rn(A[i][j], -QOFF) + (double)A2[i][j];
            float hi = (float)sum;
            float lo = (float)(sum - (double)hi);
            g_q2[(size_t)(bt + ty*2 + i) * DKEY + (bq + tx*2 + j)] = make_float2(hi, lo);
        }
}

// ------------------------------ q normalize (fp64, ILP) ------------------------------
__global__ void qnorm_kernel() {
    int row = blockIdx.x * 8 + (threadIdx.x >> 5);
    int lane = threadIdx.x & 31;
    const float2* q = g_q2 + (size_t)row * DKEY;
    double v[8];
    double s0 = 0.0, s1 = 0.0, s2 = 0.0, s3 = 0.0;
    #pragma unroll
    for (int i = 0; i < 8; i += 4) {
        float2 p0 = q[lane + i * 32];
        float2 p1 = q[lane + (i+1) * 32];
        float2 p2 = q[lane + (i+2) * 32];
        float2 p3 = q[lane + (i+3) * 32];
        v[i]   = (double)p0.x + (double)p0.y;
        v[i+1] = (double)p1.x + (double)p1.y;
        v[i+2] = (double)p2.x + (double)p2.y;
        v[i+3] = (double)p3.x + (double)p3.y;
        s0 = fma(v[i], v[i], s0);
        s1 = fma(v[i+1], v[i+1], s1);
        s2 = fma(v[i+2], v[i+2], s2);
        s3 = fma(v[i+3], v[i+3], s3);
    }
    double ss = (s0 + s1) + (s2 + s3);
    #pragma unroll
    for (int o = 16; o; o >>= 1) ss += __shfl_xor_sync(0xffffffffu, ss, o);
    double inv = 1.0 / fmax(sqrt(ss), 1e-12);
    #pragma unroll
    for (int i = 0; i < 8; i++) {
        double qn = v[i] * inv;
        float hi = (float)qn;
        float lo = (float)(qn - (double)hi);
        size_t gi = (size_t)row * DKEY + lane + i * 32;
        g_qn_hi[gi] = hi;
        g_qn_lo[gi] = lo;
        g_qb[gi] = __float2bfloat16(hi);
    }
}

// ------------------------------ sims GEMM v1b: full-K, 128x256 tile, reduced live fragments ------------------------------
#define SBM 128
#define SBN 256
#define SPAD 264
#define SIMS_SMEM ((SBM * SPAD + SBN * SPAD) * 2)

__global__ __launch_bounds__(256, 1) void sims_kernel() {
    extern __shared__ char smem_raw[];
    bf16* sQ = (bf16*)smem_raw;
    bf16* sK = sQ + SBM * SPAD;
    float* stagef = (float*)sK;

    int bm = blockIdx.y * SBM;
    int bn = blockIdx.x * SBN;
    int tid = threadIdx.x;
    int warp = tid >> 5;
    int wr = warp >> 2;
    int wc = warp & 3;

    #pragma unroll
    for (int rep = 0; rep < 16; rep++) {
        int idx = tid + rep * 256;
        int row = idx >> 5, g = idx & 31;
        *(float4*)(sQ + row * SPAD + g * 8) =
            *(const float4*)(g_qb + (size_t)(bm + row) * DKEY + g * 8);
    }
    #pragma unroll
    for (int rep = 0; rep < 32; rep++) {
        int idx = tid + rep * 256;
        int row = idx >> 5, g = idx & 31;
        *(float4*)(sK + row * SPAD + g * 8) =
            *(const float4*)(g_kb + (size_t)(bn + row) * DKEY + g * 8);
    }
    __syncthreads();

    wmma::fragment<wmma::accumulator, 16, 16, 16, float> acc[4][4];
    #pragma unroll
    for (int i = 0; i < 4; i++)
        #pragma unroll
        for (int j = 0; j < 4; j++) wmma::fill_fragment(acc[i][j], 0.0f);

    #pragma unroll
    for (int ks = 0; ks < DKEY / 16; ks++) {
        int kc = ks * 16;
        wmma::fragment<wmma::matrix_a, 16, 16, 16, bf16, wmma::row_major> a[4];
        #pragma unroll
        for (int i = 0; i < 4; i++)
            wmma::load_matrix_sync(a[i], sQ + (wr * 64 + i * 16) * SPAD + kc, SPAD);
        // two half-passes over B: only 2 live B fragments at a time (reg relief)
        #pragma unroll
        for (int half = 0; half < 2; half++) {
            wmma::fragment<wmma::matrix_b, 16, 16, 16, bf16, wmma::col_major> b[2];
            #pragma unroll
            for (int jj = 0; jj < 2; jj++)
                wmma::load_matrix_sync(b[jj], sK + (wc * 64 + (half * 2 + jj) * 16) * SPAD + kc, SPAD);
            #pragma unroll
            for (int i = 0; i < 4; i++)
                #pragma unroll
                for (int jj = 0; jj < 2; jj++)
                    wmma::mma_sync(acc[i][half * 2 + jj], a[i], b[jj], acc[i][half * 2 + jj]);
        }
    }
    __syncthreads();

    #pragma unroll
    for (int i = 0; i < 4; i++)
        #pragma unroll
        for (int j = 0; j < 4; j++)
            wmma::store_matrix_sync(stagef + (wr * 64 + i * 16) * 260 + wc * 64 + j * 16,
                                    acc[i][j], 260, wmma::mem_row_major);
    __syncthreads();

    #pragma unroll
    for (int rep = 0; rep < 16; rep++) {
        int idx = tid + rep * 256;
        int row = idx >> 5, g = idx & 31;
        const float* src = stagef + row * 260 + g * 8;
        float4 f0 = *(const float4*)src;
        float4 f1 = *(const float4*)(src + 4);
        __align__(16) bf16 tmp[8];
        tmp[0] = __float2bfloat16(f0.x); tmp[1] = __float2bfloat16(f0.y);
        tmp[2] = __float2bfloat16(f0.z); tmp[3] = __float2bfloat16(f0.w);
        tmp[4] = __float2bfloat16(f1.x); tmp[5] = __float2bfloat16(f1.y);
        tmp[6] = __float2bfloat16(f1.z); tmp[7] = __float2bfloat16(f1.w);
        *(float4*)(g_sims + (size_t)(bm + row) * NMEM + bn + g * 8) = *(float4*)tmp;

        float mx = __bfloat162float(tmp[0]);
        #pragma unroll
        for (int e = 1; e < 8; e++) mx = fmaxf(mx, __bfloat162float(tmp[e]));
        #pragma unroll
        for (int off = 1; off < 8; off <<= 1)
            mx = fmaxf(mx, __shfl_xor_sync(0xffffffffu, mx, off));
        if ((g & 7) == 0)
            g_blkmax[(size_t)(bm + row) * NCHUNK + (bn >> 6) + (g >> 3)] = __float2bfloat16(mx);
    }
}

// ------------------------------ top-64 preselect v3: chunk-max pruning, small smem ------------------------------
__device__ __forceinline__ unsigned ordkey16(unsigned u) {
    return (u & 0x8000u) ? (u ^ 0xFFFFu) : (u | 0x8000u);
}

__global__ __launch_bounds__(256) void topk_kernel() {
    int t = blockIdx.x;
    extern __shared__ unsigned short sbuf[];        // TKCAP ordkeys = 16 KB
    __shared__ unsigned short sclist[NCHUNK];
    __shared__ unsigned hist[256];
    __shared__ unsigned sh_b, sh_above, sh_KM, sh_nsel, sh_thr, sh_K1, ctrG, ctrE;
    int tid = threadIdx.x;

    hist[tid] = 0;
    __syncthreads();
    unsigned mk0, mk1;
    {
        const unsigned short* bm = (const unsigned short*)(g_blkmax + (size_t)t * NCHUNK);
        mk0 = ordkey16((unsigned)bm[tid]);
        mk1 = ordkey16((unsigned)bm[tid + 256]);
        atomicAdd(&hist[mk0 >> 8], 1u);
        atomicAdd(&hist[mk1 >> 8], 1u);
    }
    __syncthreads();
    if (tid == 0) {
        unsigned cum = 0; int b = 255;
        for (; b > 0; b--) { if (cum + hist[b] >= NCAND) break; cum += hist[b]; }
        sh_b = (unsigned)b; sh_above = cum;
    }
    __syncthreads();
    unsigned b = sh_b;
    hist[tid] = 0;
    __syncthreads();
    if ((mk0 >> 8) == b) atomicAdd(&hist[mk0 & 255u], 1u);
    if ((mk1 >> 8) == b) atomicAdd(&hist[mk1 & 255u], 1u);
    __syncthreads();
    if (tid == 0) {
        unsigned cum = sh_above; int l = 255;
        for (; l > 0; l--) { if (cum + hist[l] >= NCAND) break; cum += hist[l]; }
        sh_KM = (b << 8) | (unsigned)l;
        sh_nsel = 0;
    }
    __syncthreads();

    unsigned KM = sh_KM;
    if (mk0 >= KM) { unsigned p = atomicAdd(&sh_nsel, 1u); sclist[p] = (unsigned short)tid; }
    if (mk1 >= KM) { unsigned p = atomicAdd(&sh_nsel, 1u); sclist[p] = (unsigned short)(tid + 256); }
    __syncthreads();
    int ns = (int)sh_nsel * 64;

    hist[tid] = 0;
    __syncthreads();
    const unsigned short* row = (const unsigned short*)(g_sims + (size_t)t * NMEM);
    for (int j = tid; j < ns; j += 256) {
        int chunk = sclist[j >> 6];
        unsigned k = ordkey16((unsigned)row[chunk * 64 + (j & 63)]);
        if (j < TKCAP) sbuf[j] = (unsigned short)k;
        atomicAdd(&hist[k >> 8], 1u);
    }
    __syncthreads();
    if (tid == 0) {
        unsigned cum = 0; int bb = 255;
        for (; bb > 0; bb--) { if (cum + hist[bb] >= NCAND) break; cum += hist[bb]; }
        sh_b = (unsigned)bb; sh_above = cum;
    }
    __syncthreads();
    unsigned b2 = sh_b;
    hist[tid] = 0;
    __syncthreads();
    for (int j = tid; j < ns; j += 256) {
        unsigned k = (j < TKCAP) ? (unsigned)sbuf[j]
                   : ordkey16((unsigned)row[sclist[j >> 6] * 64 + (j & 63)]);
        if ((k >> 8) == b2) atomicAdd(&hist[k & 255u], 1u);
    }
    __syncthreads();
    if (tid == 0) {
        unsigned cum = sh_above; int l = 255;
        for (; l > 0; l--) { if (cum + hist[l] >= NCAND) break; cum += hist[l]; }
        sh_thr = (b2 << 8) | (unsigned)l;
        sh_K1 = cum;
        ctrG = 0; ctrE = 0;
    }
    __syncthreads();

    unsigned thr = sh_thr, K1 = sh_K1;
    for (int j = tid; j < ns; j += 256) {
        unsigned k = (j < TKCAP) ? (unsigned)sbuf[j]
                   : ordkey16((unsigned)row[sclist[j >> 6] * 64 + (j & 63)]);
        if (k > thr) {
            unsigned p = atomicAdd(&ctrG, 1u);
            g_cand[t * NCAND + p] = (int)sclist[j >> 6] * 64 + (j & 63);
        } else if (k == thr) {
            unsigned p = atomicAdd(&ctrE, 1u);
            if (K1 + p < NCAND) g_cand[t * NCAND + K1 + p] = (int)sclist[j >> 6] * 64 + (j & 63);
        }
    }
}

// ------------------------------ fused: exact rescore + top-32 + softmax + gather ------------------------------
__device__ __forceinline__ void kmac(float a, float b, float& s, float& c) {
    float p  = __fmul_rn(a, b);
    float e  = __fmaf_rn(a, b, -p);
    float t  = __fadd_rn(s, p);
    float bv = __fadd_rn(t, -s);
    float e1 = __fadd_rn(s, -__fadd_rn(t, -bv));
    float e2 = __fadd_rn(p, -bv);
    s = t;
    c = __fadd_rn(c, __fadd_rn(e, __fadd_rn(e1, e2)));
}

__global__ __launch_bounds__(256) void rescore_gather_kernel(const float* __restrict__ values) {
    int t = blockIdx.x;
    int tid = threadIdx.x;
    __shared__ __align__(16) float qhi[DKEY];
    __shared__ __align__(16) float qlo[DKEY];
    __shared__ float cval[NCAND];
    __shared__ int cidx[NCAND];
    __shared__ float sw[TOPK];
    __shared__ int sidx[TOPK];
    __shared__ float sval[TOPK];

    qhi[tid] = g_qn_hi[(size_t)t * DKEY + tid];
    qlo[tid] = g_qn_lo[(size_t)t * DKEY + tid];
    if (tid < NCAND) cidx[tid] = g_cand[t * NCAND + tid];
    __syncthreads();

    int c = tid >> 2, part = tid & 3;
    int ki = cidx[c];
    const float* khi = g_kn_hi + (size_t)ki * DKEY + part * 64;
    const float* klo = g_kn_lo + (size_t)ki * DKEY + part * 64;
    const float* qh = qhi + part * 64;
    const float* ql = qlo + part * 64;

    float s = 0.f, comp = 0.f, cr = 0.f;
    #pragma unroll 8
    for (int i = 0; i < 64; i++) {
        float kh = khi[i], kl = klo[i];
        float qhv = qh[i], qlv = ql[i];
        kmac(qhv, kh, s, comp);
        cr = __fmaf_rn(qhv, kl, cr);
        cr = __fmaf_rn(qlv, kh, cr);
    }
    double v = (double)s + (double)comp + (double)cr;
    v += __shfl_xor_sync(0xffffffffu, v, 1);
    v += __shfl_xor_sync(0xffffffffu, v, 2);
    if (part == 0) cval[c] = (float)v;
    __syncthreads();

    if (tid < NCAND) {
        float val = cval[tid]; int myi = cidx[tid];
        int rnk = 0;
        #pragma unroll 8
        for (int j = 0; j < NCAND; j++) {
            float u = cval[j];
            rnk += (u > val) || (u == val && cidx[j] < myi);
        }
        if (rnk < TOPK) { sval[rnk] = val; sidx[rnk] = myi; }
    }
    __syncthreads();

    if (tid < 32) {
        float val = sval[tid];
        float m = val;
        #pragma unroll
        for (int o = 16; o; o >>= 1) m = fmaxf(m, __shfl_xor_sync(0xffffffffu, m, o));
        float e = expf(val - m);
        float sum = e;
        #pragma unroll
        for (int o = 16; o; o >>= 1) sum += __shfl_xor_sync(0xffffffffu, sum, o);
        sw[tid] = e / sum;
    }
    __syncthreads();

    // gather: 256 threads x 1 float4 = 1024 floats
    float4 acc = make_float4(0.f, 0.f, 0.f, 0.f);
    #pragma unroll 8
    for (int i = 0; i < TOPK; i++) {
        const float4 vv = *((const float4*)(values + (size_t)sidx[i] * DVAL) + tid);
        float wi = sw[i];
        acc.x = fmaf(wi, vv.x, acc.x);
        acc.y = fmaf(wi, vv.y, acc.y);
        acc.z = fmaf(wi, vv.z, acc.z);
        acc.w = fmaf(wi, vv.w, acc.w);
    }
    ((float4*)(g_memout + (size_t)t * DVAL))[tid] = acc;
}

// ------------------------------ 3-term split-bf16 GEMM, double-buffered ------------------------------
template<int WHICH>
__global__ __launch_bounds__(256) void gemm_kernel(float* __restrict__ Cout) {
    constexpr int N = (WHICH == 1) ? DVAL : DMODEL;
    constexpr int K = (WHICH == 2) ? DVAL : DMODEL;
    constexpr int BM = 128, BN = 64, KC = 16;
    constexpr int NIT = K / KC;

    const bf16* Ahi = (WHICH == 2) ? g_hhi : g_xhi;
    const bf16* Alo = (WHICH == 2) ? g_hlo : g_xlo;
    const bf16* Bhi = (WHICH == 1) ? g_wghi : g_wohi;
    const bf16* Blo = (WHICH == 1) ? g_wglo : g_wolo;

    extern __shared__ char smem_raw[];
    bf16* sbuf = (bf16*)smem_raw;
    float* stage = (float*)smem_raw;

    int bm = blockIdx.y * BM;
    int bn = blockIdx.x * BN;
    int tid = threadIdx.x;
    int warp = tid >> 5;
    int wr = warp >> 1;
    int wc = warp & 1;

    wmma::fragment<wmma::accumulator, 16, 16, 16, float> acc[2][2];
    #pragma unroll
    for (int i = 0; i < 2; i++)
        #pragma unroll
        for (int j = 0; j < 2; j++) wmma::fill_fragment(acc[i][j], 0.0f);

    int ar = tid >> 1, ah = (tid & 1) * 8;
    int br = tid >> 2, bh2 = (tid & 3);

    const int OAH = 0, OAL = 2048, OBH = 4096, OBL = 5120;

    {
        const float4 va = *(const float4*)(Ahi + (size_t)(bm + ar) * K + ah);
        const float4 vb = *(const float4*)(Alo + (size_t)(bm + ar) * K + ah);
        *(float4*)(sbuf + OAH + ar * KC + ah) = va;
        *(float4*)(sbuf + OAL + ar * KC + ah) = vb;
        const bf16* bsrc = (bh2 & 2) ? Blo : Bhi;
        int bofs = (bh2 & 1) * 8;
        const float4 vc = *(const float4*)(bsrc + (size_t)(bn + br) * K + bofs);
        *(float4*)(sbuf + ((bh2 & 2) ? OBL : OBH) + br * KC + bofs) = vc;
    }
    __syncthreads();

    #pragma unroll 4
    for (int it = 0; it < NIT; it++) {
        int cur = (it & 1) * 6144;
        float4 pa, pal, pb;
        if (it + 1 < NIT) {
            int kc = (it + 1) * KC;
            pa  = *(const float4*)(Ahi + (size_t)(bm + ar) * K + kc + ah);
            pal = *(const float4*)(Alo + (size_t)(bm + ar) * K + kc + ah);
            const bf16* bsrc = (bh2 & 2) ? Blo : Bhi;
            pb  = *(const float4*)(bsrc + (size_t)(bn + br) * K + kc + (bh2 & 1) * 8);
        }

        wmma::fragment<wmma::matrix_a, 16, 16, 16, bf16, wmma::row_major> a0, a1, c0, c1;
        wmma::fragment<wmma::matrix_b, 16, 16, 16, bf16, wmma::col_major> b0, b1;

        wmma::load_matrix_sync(a0, sbuf + cur + OAH + (wr * 32 + 0) * KC, KC);
        wmma::load_matrix_sync(a1, sbuf + cur + OAH + (wr * 32 + 16) * KC, KC);
        wmma::load_matrix_sync(b0, sbuf + cur + OBH + (wc * 32 + 0) * KC, KC);
        wmma::load_matrix_sync(b1, sbuf + cur + OBH + (wc * 32 + 16) * KC, KC);
        wmma::mma_sync(acc[0][0], a0, b0, acc[0][0]);
        wmma::mma_sync(acc[0][1], a0, b1, acc[0][1]);
        wmma::mma_sync(acc[1][0], a1, b0, acc[1][0]);
        wmma::mma_sync(acc[1][1], a1, b1, acc[1][1]);

        wmma::load_matrix_sync(c0, sbuf + cur + OAL + (wr * 32 + 0) * KC, KC);
        wmma::load_matrix_sync(c1, sbuf + cur + OAL + (wr * 32 + 16) * KC, KC);
        wmma::mma_sync(acc[0][0], c0, b0, acc[0][0]);
        wmma::mma_sync(acc[0][1], c0, b1, acc[0][1]);
        wmma::mma_sync(acc[1][0], c1, b0, acc[1][0]);
        wmma::mma_sync(acc[1][1], c1, b1, acc[1][1]);

        wmma::load_matrix_sync(b0, sbuf + cur + OBL + (wc * 32 + 0) * KC, KC);
        wmma::load_matrix_sync(b1, sbuf + cur + OBL + (wc * 32 + 16) * KC, KC);
        wmma::mma_sync(acc[0][0], a0, b0, acc[0][0]);
        wmma::mma_sync(acc[0][1], a0, b1, acc[0][1]);
        wmma::mma_sync(acc[1][0], a1, b0, acc[1][0]);
        wmma::mma_sync(acc[1][1], a1, b1, acc[1][1]);

        if (it + 1 < NIT) {
            int nxt = ((it + 1) & 1) * 6144;
            *(float4*)(sbuf + nxt + OAH + ar * KC + ah) = pa;
            *(float4*)(sbuf + nxt + OAL + ar * KC + ah) = pal;
            *(float4*)(sbuf + nxt + ((bh2 & 2) ? OBL : OBH) + br * KC + (bh2 & 1) * 8) = pb;
            __syncthreads();
        }
    }

    if (WHICH == 2) {
        #pragma unroll
        for (int i = 0; i < 2; i++)
            #pragma unroll
            for (int j = 0; j < 2; j++)
                wmma::store_matrix_sync(Cout + (size_t)(bm + wr * 32 + i * 16) * N + bn + wc * 32 + j * 16,
                                        acc[i][j], N, wmma::mem_row_major);
    } else {
        __syncthreads();
        #pragma unroll
        for (int i = 0; i < 2; i++)
            #pragma unroll
            for (int j = 0; j < 2; j++)
                wmma::store_matrix_sync(stage + (wr * 32 + i * 16) * 68 + wc * 32 + j * 16,
                                        acc[i][j], 68, wmma::mem_row_major);
        __syncthreads();
        for (int e = tid; e < BM * BN; e += 256) {
            int lr = e >> 6, lc = e & 63;
            float gpre = stage[lr * 68 + lc];
            float sg = gpre / (1.0f + expf(-gpre));
            size_t gi = (size_t)(bm + lr) * N + bn + lc;
            float h = sg * g_memout[gi];
            bf16 hh = __float2bfloat16(h);
            g_hhi[gi] = hh;
            g_hlo[gi] = __float2bfloat16(h - __bfloat162float(hh));
        }
    }
}

// ------------------------------ launcher ------------------------------
extern "C" void kernel_launch(void* const* d_in, const int* in_sizes, int n_in,
                              void* d_out, int out_size) {
    const float *x = nullptr, *keys = nullptr, *values = nullptr,
                *w_q = nullptr, *w_gate = nullptr, *w_out = nullptr;
    for (int i = 0; i < n_in; i++) {
        int sz = in_sizes[i];
        const float* p = (const float*)d_in[i];
        if (sz == BS_TOK * DMODEL)      x = p;
        else if (sz == NMEM * DKEY)     keys = p;
        else if (sz == NMEM * DVAL)     values = p;
        else if (sz == DKEY * DMODEL)   w_q = p;
        else if (sz == DVAL * DMODEL) { if (!w_gate) w_gate = p; else w_out = p; }
    }
    float* out = (float*)d_out;

    cudaFuncSetAttribute(sims_kernel, cudaFuncAttributeMaxDynamicSharedMemorySize, SIMS_SMEM);

    size_t smem_g2 = 2 * 6144 * sizeof(bf16);                            // 24576 B
    size_t smem_g1 = (size_t)128 * 68 * sizeof(float);                   // 34816 B
    size_t smem_tk = TKCAP * 2;                                          // 16384 B

    // R11 launch structure (proven best) + fused rescore-gather; #4 = sims (profiled)
    knorm_kernel<<<NMEM / 8, 256>>>(keys);                                   // 1
    qexact_kernel<<<dim3(DKEY / QTN, BS_TOK / QTM), 256>>>(x, w_q);          // 2
    qnorm_kernel<<<BS_TOK / 8, 256>>>();                                     // 3
    sims_kernel<<<dim3(NMEM / SBN, BS_TOK / SBM), 256, SIMS_SMEM>>>();       // 4 <- profiled
    splitx_kernel<<<(NX + 255) / 256, 256>>>(x);                             // 5
    splitw_kernel<<<(NWG + NWO + 255) / 256, 256>>>(w_gate, w_out);          // 6
    topk_kernel<<<BS_TOK, 256, smem_tk>>>();                                 // 7
    rescore_gather_kernel<<<BS_TOK, 256>>>(values);                          // 8
    gemm_kernel<1><<<dim3(DVAL / 64, BS_TOK / 128), 256, smem_g1>>>(nullptr);// 9
    gemm_kernel<2><<<dim3(DMODEL / 64, BS_TOK / 128), 256, smem_g2>>>(out);  // 10
}

// round 16
// speedup vs baseline: 1.1211x; 1.0678x over previous
#include <cuda_runtime.h>
#include <cuda_bf16.h>
#include <mma.h>

using namespace nvcuda;

typedef __nv_bfloat16 bf16;

#define BS_TOK 4096
#define DMODEL 1024
#define NMEM   32768
#define DKEY   256
#define DVAL   1024
#define TOPK   32
#define NCAND  64
#define NCHUNK 512
#define TKCAP  8192

// ------------------------------ scratch (device globals) ------------------------------
__device__ __align__(16) float2 g_q2[BS_TOK * DKEY];
__device__ __align__(16) float  g_qn_hi[BS_TOK * DKEY];
__device__ __align__(16) float  g_qn_lo[BS_TOK * DKEY];
__device__ __align__(16) bf16   g_qb[BS_TOK * DKEY];
__device__ __align__(16) float  g_kn_hi[NMEM * DKEY];
__device__ __align__(16) float  g_kn_lo[NMEM * DKEY];
__device__ __align__(16) bf16   g_kb[NMEM * DKEY];
__device__ __align__(16) bf16   g_sims[(size_t)BS_TOK * NMEM];   // 256 MB
__device__ __align__(16) bf16   g_blkmax[BS_TOK * NCHUNK];       // 4 MB chunk maxima
__device__ int   g_cand[BS_TOK * NCAND];
__device__ __align__(16) float g_memout[BS_TOK * DVAL];
__device__ __align__(16) float g_gpre[BS_TOK * DVAL];            // 16 MB gate pre-activation
__device__ __align__(16) bf16 g_xhi[BS_TOK * DMODEL];
__device__ __align__(16) bf16 g_xlo[BS_TOK * DMODEL];
__device__ __align__(16) bf16 g_wghi[DVAL * DMODEL];
__device__ __align__(16) bf16 g_wglo[DVAL * DMODEL];
__device__ __align__(16) bf16 g_wohi[DMODEL * DVAL];
__device__ __align__(16) bf16 g_wolo[DMODEL * DVAL];
__device__ __align__(16) bf16 g_hhi[BS_TOK * DVAL];
__device__ __align__(16) bf16 g_hlo[BS_TOK * DVAL];

#define NX (BS_TOK * DMODEL)
#define NWG (DVAL * DMODEL)
#define NWO (DMODEL * DVAL)

// ------------------------------ split x / weights -> bf16 hi/lo ------------------------------
__global__ void splitx_kernel(const float* __restrict__ x) {
    int i = blockIdx.x * blockDim.x + threadIdx.x;
    if (i >= NX) return;
    float v = x[i];
    bf16 h = __float2bfloat16(v);
    g_xhi[i] = h;
    g_xlo[i] = __float2bfloat16(__fadd_rn(v, -__bfloat162float(h)));
}

__global__ void splitw_kernel(const float* __restrict__ wg,
                              const float* __restrict__ wo) {
    int i = blockIdx.x * blockDim.x + threadIdx.x;
    const float* src; bf16 *hi, *lo; int j;
    if (i < NWG) { src = wg; hi = g_wghi; lo = g_wglo; j = i; }
    else if (i < NWG + NWO) { src = wo; hi = g_wohi; lo = g_wolo; j = i - NWG; }
    else return;
    float v = src[j];
    bf16 h = __float2bfloat16(v);
    hi[j] = h;
    lo[j] = __float2bfloat16(__fadd_rn(v, -__bfloat162float(h)));
}

// ------------------------------ key normalize (double-float fp32) ------------------------------
__global__ __launch_bounds__(256) void knorm_kernel(const float* __restrict__ keys) {
    int row = blockIdx.x * 8 + (threadIdx.x >> 5);
    int lane = threadIdx.x & 31;
    const float4* s4 = (const float4*)(keys + (size_t)row * DKEY);
    float4 a = s4[lane], b = s4[lane + 32];
    float v[8] = {a.x, a.y, a.z, a.w, b.x, b.y, b.z, b.w};

    float s = 0.f, c = 0.f;
    #pragma unroll
    for (int i = 0; i < 8; i++) {
        float p = __fmul_rn(v[i], v[i]);
        float e = __fmaf_rn(v[i], v[i], -p);
        float t  = __fadd_rn(s, p);
        float bv = __fadd_rn(t, -s);
        float err = __fadd_rn(__fadd_rn(s, -__fadd_rn(t, -bv)), __fadd_rn(p, -bv));
        s = t;
        c = __fadd_rn(c, __fadd_rn(err, e));
    }
    double d = (double)s + (double)c;
    #pragma unroll
    for (int o = 16; o; o >>= 1) d += __shfl_xor_sync(0xffffffffu, d, o);
    double inv = 1.0 / fmax(sqrt(d), 1e-12);
    float ih = (float)inv;
    float il = (float)(inv - (double)ih);

    float h2[8], l2[8];
    #pragma unroll
    for (int i = 0; i < 8; i++) {
        float p = __fmul_rn(v[i], ih);
        float e = __fmaf_rn(v[i], ih, -p);
        float lo = __fmaf_rn(v[i], il, e);
        float hh = __fadd_rn(p, lo);
        h2[i] = hh;
        l2[i] = __fadd_rn(lo, -__fadd_rn(hh, -p));
    }
    float4* dh = (float4*)(g_kn_hi + (size_t)row * DKEY);
    float4* dl = (float4*)(g_kn_lo + (size_t)row * DKEY);
    dh[lane]      = make_float4(h2[0], h2[1], h2[2], h2[3]);
    dh[lane + 32] = make_float4(h2[4], h2[5], h2[6], h2[7]);
    dl[lane]      = make_float4(l2[0], l2[1], l2[2], l2[3]);
    dl[lane + 32] = make_float4(l2[4], l2[5], l2[6], l2[7]);
    __nv_bfloat162* db = (__nv_bfloat162*)(g_kb + (size_t)row * DKEY);
    db[lane*2 + 0]  = __nv_bfloat162(__float2bfloat16(h2[0]), __float2bfloat16(h2[1]));
    db[lane*2 + 1]  = __nv_bfloat162(__float2bfloat16(h2[2]), __float2bfloat16(h2[3]));
    db[64 + lane*2 + 0] = __nv_bfloat162(__float2bfloat16(h2[4]), __float2bfloat16(h2[5]));
    db[64 + lane*2 + 1] = __nv_bfloat162(__float2bfloat16(h2[6]), __float2bfloat16(h2[7]));
}

// ------------------------------ exact q GEMM v2: 32x32 tile, offset-accumulator ------------------------------
#define QTM 32
#define QTN 32
#define QTK 32
#define QOFF 1024.0f

__global__ __launch_bounds__(256) void qexact_kernel(const float* __restrict__ x,
                                                     const float* __restrict__ wq) {
    __shared__ float sX[QTK][QTM + 4];
    __shared__ float sW[QTK][QTN + 4];
    int bt = blockIdx.y * QTM;
    int bq = blockIdx.x * QTN;
    int tid = threadIdx.x;
    int ty = tid >> 4;
    int tx = tid & 15;

    float A[2][2], A2[2][2];
    #pragma unroll
    for (int i = 0; i < 2; i++)
        #pragma unroll
        for (int j = 0; j < 2; j++) { A[i][j] = QOFF; A2[i][j] = 0.f; }

    int lrow = tid >> 3;
    int lc4 = (tid & 7) * 4;

    for (int kc = 0; kc < DMODEL; kc += QTK) {
        float4 v = *(const float4*)(x + (size_t)(bt + lrow) * DMODEL + kc + lc4);
        sX[lc4+0][lrow] = v.x; sX[lc4+1][lrow] = v.y;
        sX[lc4+2][lrow] = v.z; sX[lc4+3][lrow] = v.w;
        float4 w = *(const float4*)(wq + (size_t)(bq + lrow) * DMODEL + kc + lc4);
        sW[lc4+0][lrow] = w.x; sW[lc4+1][lrow] = w.y;
        sW[lc4+2][lrow] = w.z; sW[lc4+3][lrow] = w.w;
        __syncthreads();
        #pragma unroll 8
        for (int k = 0; k < QTK; k++) {
            float2 rx = *(const float2*)&sX[k][ty * 2];
            float2 rw = *(const float2*)&sW[k][tx * 2];
            float ax[2] = {rx.x, rx.y};
            float bw[2] = {rw.x, rw.y};
            #pragma unroll
            for (int i = 0; i < 2; i++)
                #pragma unroll
                for (int j = 0; j < 2; j++) {
                    float p = __fmul_rn(ax[i], bw[j]);
                    float e = __fmaf_rn(ax[i], bw[j], -p);
                    float t = __fadd_rn(A[i][j], p);
                    float z = __fadd_rn(t, -A[i][j]);
                    float r = __fadd_rn(p, -z);
                    A[i][j] = t;
                    A2[i][j] = __fadd_rn(A2[i][j], __fadd_rn(r, e));
                }
        }
        __syncthreads();
    }

    #pragma unroll
    for (int i = 0; i < 2; i++)
        #pragma unroll
        for (int j = 0; j < 2; j++) {
            double sum = (double)__fadd_rn(A[i][j], -QOFF) + (double)A2[i][j];
            float hi = (float)sum;
            float lo = (float)(sum - (double)hi);
            g_q2[(size_t)(bt + ty*2 + i) * DKEY + (bq + tx*2 + j)] = make_float2(hi, lo);
        }
}

// ------------------------------ q normalize (fp64, ILP) ------------------------------
__global__ void qnorm_kernel() {
    int row = blockIdx.x * 8 + (threadIdx.x >> 5);
    int lane = threadIdx.x & 31;
    const float2* q = g_q2 + (size_t)row * DKEY;
    double v[8];
    double s0 = 0.0, s1 = 0.0, s2 = 0.0, s3 = 0.0;
    #pragma unroll
    for (int i = 0; i < 8; i += 4) {
        float2 p0 = q[lane + i * 32];
        float2 p1 = q[lane + (i+1) * 32];
        float2 p2 = q[lane + (i+2) * 32];
        float2 p3 = q[lane + (i+3) * 32];
        v[i]   = (double)p0.x + (double)p0.y;
        v[i+1] = (double)p1.x + (double)p1.y;
        v[i+2] = (double)p2.x + (double)p2.y;
        v[i+3] = (double)p3.x + (double)p3.y;
        s0 = fma(v[i], v[i], s0);
        s1 = fma(v[i+1], v[i+1], s1);
        s2 = fma(v[i+2], v[i+2], s2);
        s3 = fma(v[i+3], v[i+3], s3);
    }
    double ss = (s0 + s1) + (s2 + s3);
    #pragma unroll
    for (int o = 16; o; o >>= 1) ss += __shfl_xor_sync(0xffffffffu, ss, o);
    double inv = 1.0 / fmax(sqrt(ss), 1e-12);
    #pragma unroll
    for (int i = 0; i < 8; i++) {
        double qn = v[i] * inv;
        float hi = (float)qn;
        float lo = (float)(qn - (double)hi);
        size_t gi = (size_t)row * DKEY + lane + i * 32;
        g_qn_hi[gi] = hi;
        g_qn_lo[gi] = lo;
        g_qb[gi] = __float2bfloat16(hi);
    }
}

// ------------------------------ sims GEMM v1b: full-K, 128x256 tile (proven) ------------------------------
#define SBM 128
#define SBN 256
#define SPAD 264
#define SIMS_SMEM ((SBM * SPAD + SBN * SPAD) * 2)

__global__ __launch_bounds__(256, 1) void sims_kernel() {
    extern __shared__ char smem_raw[];
    bf16* sQ = (bf16*)smem_raw;
    bf16* sK = sQ + SBM * SPAD;
    float* stagef = (float*)sK;

    int bm = blockIdx.y * SBM;
    int bn = blockIdx.x * SBN;
    int tid = threadIdx.x;
    int warp = tid >> 5;
    int wr = warp >> 2;
    int wc = warp & 3;

    #pragma unroll
    for (int rep = 0; rep < 16; rep++) {
        int idx = tid + rep * 256;
        int row = idx >> 5, g = idx & 31;
        *(float4*)(sQ + row * SPAD + g * 8) =
            *(const float4*)(g_qb + (size_t)(bm + row) * DKEY + g * 8);
    }
    #pragma unroll
    for (int rep = 0; rep < 32; rep++) {
        int idx = tid + rep * 256;
        int row = idx >> 5, g = idx & 31;
        *(float4*)(sK + row * SPAD + g * 8) =
            *(const float4*)(g_kb + (size_t)(bn + row) * DKEY + g * 8);
    }
    __syncthreads();

    wmma::fragment<wmma::accumulator, 16, 16, 16, float> acc[4][4];
    #pragma unroll
    for (int i = 0; i < 4; i++)
        #pragma unroll
        for (int j = 0; j < 4; j++) wmma::fill_fragment(acc[i][j], 0.0f);

    #pragma unroll
    for (int ks = 0; ks < DKEY / 16; ks++) {
        int kc = ks * 16;
        wmma::fragment<wmma::matrix_a, 16, 16, 16, bf16, wmma::row_major> a[4];
        #pragma unroll
        for (int i = 0; i < 4; i++)
            wmma::load_matrix_sync(a[i], sQ + (wr * 64 + i * 16) * SPAD + kc, SPAD);
        #pragma unroll
        for (int half = 0; half < 2; half++) {
            wmma::fragment<wmma::matrix_b, 16, 16, 16, bf16, wmma::col_major> b[2];
            #pragma unroll
            for (int jj = 0; jj < 2; jj++)
                wmma::load_matrix_sync(b[jj], sK + (wc * 64 + (half * 2 + jj) * 16) * SPAD + kc, SPAD);
            #pragma unroll
            for (int i = 0; i < 4; i++)
                #pragma unroll
                for (int jj = 0; jj < 2; jj++)
                    wmma::mma_sync(acc[i][half * 2 + jj], a[i], b[jj], acc[i][half * 2 + jj]);
        }
    }
    __syncthreads();

    #pragma unroll
    for (int i = 0; i < 4; i++)
        #pragma unroll
        for (int j = 0; j < 4; j++)
            wmma::store_matrix_sync(stagef + (wr * 64 + i * 16) * 260 + wc * 64 + j * 16,
                                    acc[i][j], 260, wmma::mem_row_major);
    __syncthreads();

    #pragma unroll
    for (int rep = 0; rep < 16; rep++) {
        int idx = tid + rep * 256;
        int row = idx >> 5, g = idx & 31;
        const float* src = stagef + row * 260 + g * 8;
        float4 f0 = *(const float4*)src;
        float4 f1 = *(const float4*)(src + 4);
        __align__(16) bf16 tmp[8];
        tmp[0] = __float2bfloat16(f0.x); tmp[1] = __float2bfloat16(f0.y);
        tmp[2] = __float2bfloat16(f0.z); tmp[3] = __float2bfloat16(f0.w);
        tmp[4] = __float2bfloat16(f1.x); tmp[5] = __float2bfloat16(f1.y);
        tmp[6] = __float2bfloat16(f1.z); tmp[7] = __float2bfloat16(f1.w);
        *(float4*)(g_sims + (size_t)(bm + row) * NMEM + bn + g * 8) = *(float4*)tmp;

        float mx = __bfloat162float(tmp[0]);
        #pragma unroll
        for (int e = 1; e < 8; e++) mx = fmaxf(mx, __bfloat162float(tmp[e]));
        #pragma unroll
        for (int off = 1; off < 8; off <<= 1)
            mx = fmaxf(mx, __shfl_xor_sync(0xffffffffu, mx, off));
        if ((g & 7) == 0)
            g_blkmax[(size_t)(bm + row) * NCHUNK + (bn >> 6) + (g >> 3)] = __float2bfloat16(mx);
    }
}

// ------------------------------ top-64 preselect v3: chunk-max pruning ------------------------------
__device__ __forceinline__ unsigned ordkey16(unsigned u) {
    return (u & 0x8000u) ? (u ^ 0xFFFFu) : (u | 0x8000u);
}

__global__ __launch_bounds__(256) void topk_kernel() {
    int t = blockIdx.x;
    extern __shared__ unsigned short sbuf[];
    __shared__ unsigned short sclist[NCHUNK];
    __shared__ unsigned hist[256];
    __shared__ unsigned sh_b, sh_above, sh_KM, sh_nsel, sh_thr, sh_K1, ctrG, ctrE;
    int tid = threadIdx.x;

    hist[tid] = 0;
    __syncthreads();
    unsigned mk0, mk1;
    {
        const unsigned short* bm = (const unsigned short*)(g_blkmax + (size_t)t * NCHUNK);
        mk0 = ordkey16((unsigned)bm[tid]);
        mk1 = ordkey16((unsigned)bm[tid + 256]);
        atomicAdd(&hist[mk0 >> 8], 1u);
        atomicAdd(&hist[mk1 >> 8], 1u);
    }
    __syncthreads();
    if (tid == 0) {
        unsigned cum = 0; int b = 255;
        for (; b > 0; b--) { if (cum + hist[b] >= NCAND) break; cum += hist[b]; }
        sh_b = (unsigned)b; sh_above = cum;
    }
    __syncthreads();
    unsigned b = sh_b;
    hist[tid] = 0;
    __syncthreads();
    if ((mk0 >> 8) == b) atomicAdd(&hist[mk0 & 255u], 1u);
    if ((mk1 >> 8) == b) atomicAdd(&hist[mk1 & 255u], 1u);
    __syncthreads();
    if (tid == 0) {
        unsigned cum = sh_above; int l = 255;
        for (; l > 0; l--) { if (cum + hist[l] >= NCAND) break; cum += hist[l]; }
        sh_KM = (b << 8) | (unsigned)l;
        sh_nsel = 0;
    }
    __syncthreads();

    unsigned KM = sh_KM;
    if (mk0 >= KM) { unsigned p = atomicAdd(&sh_nsel, 1u); sclist[p] = (unsigned short)tid; }
    if (mk1 >= KM) { unsigned p = atomicAdd(&sh_nsel, 1u); sclist[p] = (unsigned short)(tid + 256); }
    __syncthreads();
    int ns = (int)sh_nsel * 64;

    hist[tid] = 0;
    __syncthreads();
    const unsigned short* row = (const unsigned short*)(g_sims + (size_t)t * NMEM);
    for (int j = tid; j < ns; j += 256) {
        int chunk = sclist[j >> 6];
        unsigned k = ordkey16((unsigned)row[chunk * 64 + (j & 63)]);
        if (j < TKCAP) sbuf[j] = (unsigned short)k;
        atomicAdd(&hist[k >> 8], 1u);
    }
    __syncthreads();
    if (tid == 0) {
        unsigned cum = 0; int bb = 255;
        for (; bb > 0; bb--) { if (cum + hist[bb] >= NCAND) break; cum += hist[bb]; }
        sh_b = (unsigned)bb; sh_above = cum;
    }
    __syncthreads();
    unsigned b2 = sh_b;
    hist[tid] = 0;
    __syncthreads();
    for (int j = tid; j < ns; j += 256) {
        unsigned k = (j < TKCAP) ? (unsigned)sbuf[j]
                   : ordkey16((unsigned)row[sclist[j >> 6] * 64 + (j & 63)]);
        if ((k >> 8) == b2) atomicAdd(&hist[k & 255u], 1u);
    }
    __syncthreads();
    if (tid == 0) {
        unsigned cum = sh_above; int l = 255;
        for (; l > 0; l--) { if (cum + hist[l] >= NCAND) break; cum += hist[l]; }
        sh_thr = (b2 << 8) | (unsigned)l;
        sh_K1 = cum;
        ctrG = 0; ctrE = 0;
    }
    __syncthreads();

    unsigned thr = sh_thr, K1 = sh_K1;
    for (int j = tid; j < ns; j += 256) {
        unsigned k = (j < TKCAP) ? (unsigned)sbuf[j]
                   : ordkey16((unsigned)row[sclist[j >> 6] * 64 + (j & 63)]);
        if (k > thr) {
            unsigned p = atomicAdd(&ctrG, 1u);
            g_cand[t * NCAND + p] = (int)sclist[j >> 6] * 64 + (j & 63);
        } else if (k == thr) {
            unsigned p = atomicAdd(&ctrE, 1u);
            if (K1 + p < NCAND) g_cand[t * NCAND + K1 + p] = (int)sclist[j >> 6] * 64 + (j & 63);
        }
    }
}

// ------------------------------ fused: exact rescore + top-32 + softmax + gather ------------------------------
__device__ __forceinline__ void kmac(float a, float b, float& s, float& c) {
    float p  = __fmul_rn(a, b);
    float e  = __fmaf_rn(a, b, -p);
    float t  = __fadd_rn(s, p);
    float bv = __fadd_rn(t, -s);
    float e1 = __fadd_rn(s, -__fadd_rn(t, -bv));
    float e2 = __fadd_rn(p, -bv);
    s = t;
    c = __fadd_rn(c, __fadd_rn(e, __fadd_rn(e1, e2)));
}

__global__ __launch_bounds__(256) void rescore_gather_kernel(const float* __restrict__ values) {
    int t = blockIdx.x;
    int tid = threadIdx.x;
    __shared__ __align__(16) float qhi[DKEY];
    __shared__ __align__(16) float qlo[DKEY];
    __shared__ float cval[NCAND];
    __shared__ int cidx[NCAND];
    __shared__ float sw[TOPK];
    __shared__ int sidx[TOPK];
    __shared__ float sval[TOPK];

    qhi[tid] = g_qn_hi[(size_t)t * DKEY + tid];
    qlo[tid] = g_qn_lo[(size_t)t * DKEY + tid];
    if (tid < NCAND) cidx[tid] = g_cand[t * NCAND + tid];
    __syncthreads();

    int c = tid >> 2, part = tid & 3;
    int ki = cidx[c];
    const float* khi = g_kn_hi + (size_t)ki * DKEY + part * 64;
    const float* klo = g_kn_lo + (size_t)ki * DKEY + part * 64;
    const float* qh = qhi + part * 64;
    const float* ql = qlo + part * 64;

    float s = 0.f, comp = 0.f, cr = 0.f;
    #pragma unroll 8
    for (int i = 0; i < 64; i++) {
        float kh = khi[i], kl = klo[i];
        float qhv = qh[i], qlv = ql[i];
        kmac(qhv, kh, s, comp);
        cr = __fmaf_rn(qhv, kl, cr);
        cr = __fmaf_rn(qlv, kh, cr);
    }
    double v = (double)s + (double)comp + (double)cr;
    v += __shfl_xor_sync(0xffffffffu, v, 1);
    v += __shfl_xor_sync(0xffffffffu, v, 2);
    if (part == 0) cval[c] = (float)v;
    __syncthreads();

    if (tid < NCAND) {
        float val = cval[tid]; int myi = cidx[tid];
        int rnk = 0;
        #pragma unroll 8
        for (int j = 0; j < NCAND; j++) {
            float u = cval[j];
            rnk += (u > val) || (u == val && cidx[j] < myi);
        }
        if (rnk < TOPK) { sval[rnk] = val; sidx[rnk] = myi; }
    }
    __syncthreads();

    if (tid < 32) {
        float val = sval[tid];
        float m = val;
        #pragma unroll
        for (int o = 16; o; o >>= 1) m = fmaxf(m, __shfl_xor_sync(0xffffffffu, m, o));
        float e = expf(val - m);
        float sum = e;
        #pragma unroll
        for (int o = 16; o; o >>= 1) sum += __shfl_xor_sync(0xffffffffu, sum, o);
        sw[tid] = e / sum;
    }
    __syncthreads();

    float4 acc = make_float4(0.f, 0.f, 0.f, 0.f);
    #pragma unroll 8
    for (int i = 0; i < TOPK; i++) {
        const float4 vv = *((const float4*)(values + (size_t)sidx[i] * DVAL) + tid);
        float wi = sw[i];
        acc.x = fmaf(wi, vv.x, acc.x);
        acc.y = fmaf(wi, vv.y, acc.y);
        acc.z = fmaf(wi, vv.z, acc.z);
        acc.w = fmaf(wi, vv.w, acc.w);
    }
    ((float4*)(g_memout + (size_t)t * DVAL))[tid] = acc;
}

// ------------------------------ h epilogue: h = silu(gpre) * memout -> hhi/hlo ------------------------------
__global__ void hepi_kernel() {
    int i = blockIdx.x * blockDim.x + threadIdx.x;   // per float4 group
    float4 g = ((const float4*)g_gpre)[i];
    float4 m = ((const float4*)g_memout)[i];
    float hv[4];
    hv[0] = (g.x / (1.0f + expf(-g.x))) * m.x;
    hv[1] = (g.y / (1.0f + expf(-g.y))) * m.y;
    hv[2] = (g.z / (1.0f + expf(-g.z))) * m.z;
    hv[3] = (g.w / (1.0f + expf(-g.w))) * m.w;
    __align__(8) bf16 hh[4], hl[4];
    #pragma unroll
    for (int e = 0; e < 4; e++) {
        bf16 h = __float2bfloat16(hv[e]);
        hh[e] = h;
        hl[e] = __float2bfloat16(__fadd_rn(hv[e], -__bfloat162float(h)));
    }
    *(float2*)(g_hhi + (size_t)i * 4) = *(float2*)hh;
    *(float2*)(g_hlo + (size_t)i * 4) = *(float2*)hl;
}

// ------------------------------ 3-term split-bf16 GEMM, double-buffered, direct fp32 store ------------------------------
// WHICH: 1 = gate matmul (A=x, B=w_gate) -> g_gpre;  2 = out (A=h, B=w_out) -> Cout
template<int WHICH>
__global__ __launch_bounds__(256) void gemm_kernel(float* __restrict__ Cout) {
    constexpr int N = (WHICH == 1) ? DVAL : DMODEL;
    constexpr int K = (WHICH == 2) ? DVAL : DMODEL;
    constexpr int BM = 128, BN = 64, KC = 16;
    constexpr int NIT = K / KC;

    const bf16* Ahi = (WHICH == 2) ? g_hhi : g_xhi;
    const bf16* Alo = (WHICH == 2) ? g_hlo : g_xlo;
    const bf16* Bhi = (WHICH == 1) ? g_wghi : g_wohi;
    const bf16* Blo = (WHICH == 1) ? g_wglo : g_wolo;

    extern __shared__ char smem_raw[];
    bf16* sbuf = (bf16*)smem_raw;

    int bm = blockIdx.y * BM;
    int bn = blockIdx.x * BN;
    int tid = threadIdx.x;
    int warp = tid >> 5;
    int wr = warp >> 1;
    int wc = warp & 1;

    wmma::fragment<wmma::accumulator, 16, 16, 16, float> acc[2][2];
    #pragma unroll
    for (int i = 0; i < 2; i++)
        #pragma unroll
        for (int j = 0; j < 2; j++) wmma::fill_fragment(acc[i][j], 0.0f);

    int ar = tid >> 1, ah = (tid & 1) * 8;
    int br = tid >> 2, bh2 = (tid & 3);

    const int OAH = 0, OAL = 2048, OBH = 4096, OBL = 5120;

    {
        const float4 va = *(const float4*)(Ahi + (size_t)(bm + ar) * K + ah);
        const float4 vb = *(const float4*)(Alo + (size_t)(bm + ar) * K + ah);
        *(float4*)(sbuf + OAH + ar * KC + ah) = va;
        *(float4*)(sbuf + OAL + ar * KC + ah) = vb;
        const bf16* bsrc = (bh2 & 2) ? Blo : Bhi;
        int bofs = (bh2 & 1) * 8;
        const float4 vc = *(const float4*)(bsrc + (size_t)(bn + br) * K + bofs);
        *(float4*)(sbuf + ((bh2 & 2) ? OBL : OBH) + br * KC + bofs) = vc;
    }
    __syncthreads();

    #pragma unroll 4
    for (int it = 0; it < NIT; it++) {
        int cur = (it & 1) * 6144;
        float4 pa, pal, pb;
        if (it + 1 < NIT) {
            int kc = (it + 1) * KC;
            pa  = *(const float4*)(Ahi + (size_t)(bm + ar) * K + kc + ah);
            pal = *(const float4*)(Alo + (size_t)(bm + ar) * K + kc + ah);
            const bf16* bsrc = (bh2 & 2) ? Blo : Bhi;
            pb  = *(const float4*)(bsrc + (size_t)(bn + br) * K + kc + (bh2 & 1) * 8);
        }

        wmma::fragment<wmma::matrix_a, 16, 16, 16, bf16, wmma::row_major> a0, a1, c0, c1;
        wmma::fragment<wmma::matrix_b, 16, 16, 16, bf16, wmma::col_major> b0, b1;

        wmma::load_matrix_sync(a0, sbuf + cur + OAH + (wr * 32 + 0) * KC, KC);
        wmma::load_matrix_sync(a1, sbuf + cur + OAH + (wr * 32 + 16) * KC, KC);
        wmma::load_matrix_sync(b0, sbuf + cur + OBH + (wc * 32 + 0) * KC, KC);
        wmma::load_matrix_sync(b1, sbuf + cur + OBH + (wc * 32 + 16) * KC, KC);
        wmma::mma_sync(acc[0][0], a0, b0, acc[0][0]);
        wmma::mma_sync(acc[0][1], a0, b1, acc[0][1]);
        wmma::mma_sync(acc[1][0], a1, b0, acc[1][0]);
        wmma::mma_sync(acc[1][1], a1, b1, acc[1][1]);

        wmma::load_matrix_sync(c0, sbuf + cur + OAL + (wr * 32 + 0) * KC, KC);
        wmma::load_matrix_sync(c1, sbuf + cur + OAL + (wr * 32 + 16) * KC, KC);
        wmma::mma_sync(acc[0][0], c0, b0, acc[0][0]);
        wmma::mma_sync(acc[0][1], c0, b1, acc[0][1]);
        wmma::mma_sync(acc[1][0], c1, b0, acc[1][0]);
        wmma::mma_sync(acc[1][1], c1, b1, acc[1][1]);

        wmma::load_matrix_sync(b0, sbuf + cur + OBL + (wc * 32 + 0) * KC, KC);
        wmma::load_matrix_sync(b1, sbuf + cur + OBL + (wc * 32 + 16) * KC, KC);
        wmma::mma_sync(acc[0][0], a0, b0, acc[0][0]);
        wmma::mma_sync(acc[0][1], a0, b1, acc[0][1]);
        wmma::mma_sync(acc[1][0], a1, b0, acc[1][0]);
        wmma::mma_sync(acc[1][1], a1, b1, acc[1][1]);

        if (it + 1 < NIT) {
            int nxt = ((it + 1) & 1) * 6144;
            *(float4*)(sbuf + nxt + OAH + ar * KC + ah) = pa;
            *(float4*)(sbuf + nxt + OAL + ar * KC + ah) = pal;
            *(float4*)(sbuf + nxt + ((bh2 & 2) ? OBL : OBH) + br * KC + (bh2 & 1) * 8) = pb;
            __syncthreads();
        }
    }

    #pragma unroll
    for (int i = 0; i < 2; i++)
        #pragma unroll
        for (int j = 0; j < 2; j++)
            wmma::store_matrix_sync(Cout + (size_t)(bm + wr * 32 + i * 16) * N + bn + wc * 32 + j * 16,
                                    acc[i][j], N, wmma::mem_row_major);
}

// ------------------------------ streams / events (host objects, static init) ------------------------------
static cudaStream_t g_s2;
static cudaEvent_t g_evFork, g_evK, g_evG;
namespace {
struct StreamInit {
    StreamInit() {
        cudaStreamCreateWithFlags(&g_s2, cudaStreamNonBlocking);
        cudaEventCreateWithFlags(&g_evFork, cudaEventDisableTiming);
        cudaEventCreateWithFlags(&g_evK, cudaEventDisableTiming);
        cudaEventCreateWithFlags(&g_evG, cudaEventDisableTiming);
    }
};
StreamInit g_si;
}

// ------------------------------ launcher (2-stream overlap) ------------------------------
extern "C" void kernel_launch(void* const* d_in, const int* in_sizes, int n_in,
                              void* d_out, int out_size) {
    const float *x = nullptr, *keys = nullptr, *values = nullptr,
                *w_q = nullptr, *w_gate = nullptr, *w_out = nullptr;
    for (int i = 0; i < n_in; i++) {
        int sz = in_sizes[i];
        const float* p = (const float*)d_in[i];
        if (sz == BS_TOK * DMODEL)      x = p;
        else if (sz == NMEM * DKEY)     keys = p;
        else if (sz == NMEM * DVAL)     values = p;
        else if (sz == DKEY * DMODEL)   w_q = p;
        else if (sz == DVAL * DMODEL) { if (!w_gate) w_gate = p; else w_out = p; }
    }
    float* out = (float*)d_out;
    float* gpre;
    cudaGetSymbolAddress((void**)&gpre, g_gpre);

    cudaFuncSetAttribute(sims_kernel, cudaFuncAttributeMaxDynamicSharedMemorySize, SIMS_SMEM);

    size_t smem_g = 2 * 6144 * sizeof(bf16);    // 24576 B
    size_t smem_tk = TKCAP * 2;                 // 16384 B

    // fork side stream
    cudaEventRecord(g_evFork, 0);
    cudaStreamWaitEvent(g_s2, g_evFork, 0);

    // side stream: knorm (feeds sims), then splits + gate matmul (feeds hepi)
    knorm_kernel<<<NMEM / 8, 256, 0, g_s2>>>(keys);
    cudaEventRecord(g_evK, g_s2);
    splitx_kernel<<<(NX + 255) / 256, 256, 0, g_s2>>>(x);
    splitw_kernel<<<(NWG + NWO + 255) / 256, 256, 0, g_s2>>>(w_gate, w_out);
    gemm_kernel<1><<<dim3(DVAL / 64, BS_TOK / 128), 256, smem_g, g_s2>>>(gpre);
    cudaEventRecord(g_evG, g_s2);

    // main stream: critical path
    qexact_kernel<<<dim3(DKEY / QTN, BS_TOK / QTM), 256>>>(x, w_q);
    qnorm_kernel<<<BS_TOK / 8, 256>>>();
    cudaStreamWaitEvent(0, g_evK, 0);
    sims_kernel<<<dim3(NMEM / SBN, BS_TOK / SBM), 256, SIMS_SMEM>>>();
    topk_kernel<<<BS_TOK, 256, smem_tk>>>();
    rescore_gather_kernel<<<BS_TOK, 256>>>(values);
    cudaStreamWaitEvent(0, g_evG, 0);
    hepi_kernel<<<BS_TOK * DVAL / 4 / 256, 256>>>();
    gemm_kernel<2><<<dim3(DMODEL / 64, BS_TOK / 128), 256, smem_g>>>(out);
}

// round 17
// speedup vs baseline: 1.1401x; 1.0169x over previous
#include <cuda_runtime.h>
#include <cuda_bf16.h>
#include <mma.h>

using namespace nvcuda;

typedef __nv_bfloat16 bf16;

#define BS_TOK 4096
#define DMODEL 1024
#define NMEM   32768
#define DKEY   256
#define DVAL   1024
#define TOPK   32
#define NCAND  64
#define NCHUNK 512
#define TKCAP  8192

// ------------------------------ scratch (device globals) ------------------------------
__device__ __align__(16) float2 g_q2[BS_TOK * DKEY];
__device__ __align__(16) float  g_qn_hi[BS_TOK * DKEY];
__device__ __align__(16) float  g_qn_lo[BS_TOK * DKEY];
__device__ __align__(16) bf16   g_qb[BS_TOK * DKEY];
__device__ __align__(16) float  g_kn_hi[NMEM * DKEY];
__device__ __align__(16) float  g_kn_lo[NMEM * DKEY];
__device__ __align__(16) bf16   g_kb[NMEM * DKEY];
__device__ __align__(16) bf16   g_sims[(size_t)BS_TOK * NMEM];   // 256 MB
__device__ __align__(16) bf16   g_blkmax[BS_TOK * NCHUNK];       // 4 MB chunk maxima
__device__ int   g_cand[BS_TOK * NCAND];
__device__ __align__(16) float g_memout[BS_TOK * DVAL];
__device__ __align__(16) float g_gpre[BS_TOK * DVAL];            // 16 MB gate pre-activation
__device__ __align__(16) bf16 g_xhi[BS_TOK * DMODEL];
__device__ __align__(16) bf16 g_xlo[BS_TOK * DMODEL];
__device__ __align__(16) bf16 g_wghi[DVAL * DMODEL];
__device__ __align__(16) bf16 g_wglo[DVAL * DMODEL];
__device__ __align__(16) bf16 g_wohi[DMODEL * DVAL];
__device__ __align__(16) bf16 g_wolo[DMODEL * DVAL];
__device__ __align__(16) bf16 g_hhi[BS_TOK * DVAL];
__device__ __align__(16) bf16 g_hlo[BS_TOK * DVAL];

#define NX (BS_TOK * DMODEL)
#define NWG (DVAL * DMODEL)
#define NWO (DMODEL * DVAL)

// ------------------------------ split x / weights -> bf16 hi/lo ------------------------------
__global__ void splitx_kernel(const float* __restrict__ x) {
    int i = blockIdx.x * blockDim.x + threadIdx.x;
    if (i >= NX) return;
    float v = x[i];
    bf16 h = __float2bfloat16(v);
    g_xhi[i] = h;
    g_xlo[i] = __float2bfloat16(__fadd_rn(v, -__bfloat162float(h)));
}

__global__ void splitw_kernel(const float* __restrict__ wg,
                              const float* __restrict__ wo) {
    int i = blockIdx.x * blockDim.x + threadIdx.x;
    const float* src; bf16 *hi, *lo; int j;
    if (i < NWG) { src = wg; hi = g_wghi; lo = g_wglo; j = i; }
    else if (i < NWG + NWO) { src = wo; hi = g_wohi; lo = g_wolo; j = i - NWG; }
    else return;
    float v = src[j];
    bf16 h = __float2bfloat16(v);
    hi[j] = h;
    lo[j] = __float2bfloat16(__fadd_rn(v, -__bfloat162float(h)));
}

// ------------------------------ key normalize (double-float fp32) ------------------------------
__global__ __launch_bounds__(256) void knorm_kernel(const float* __restrict__ keys) {
    int row = blockIdx.x * 8 + (threadIdx.x >> 5);
    int lane = threadIdx.x & 31;
    const float4* s4 = (const float4*)(keys + (size_t)row * DKEY);
    float4 a = s4[lane], b = s4[lane + 32];
    float v[8] = {a.x, a.y, a.z, a.w, b.x, b.y, b.z, b.w};

    float s = 0.f, c = 0.f;
    #pragma unroll
    for (int i = 0; i < 8; i++) {
        float p = __fmul_rn(v[i], v[i]);
        float e = __fmaf_rn(v[i], v[i], -p);
        float t  = __fadd_rn(s, p);
        float bv = __fadd_rn(t, -s);
        float err = __fadd_rn(__fadd_rn(s, -__fadd_rn(t, -bv)), __fadd_rn(p, -bv));
        s = t;
        c = __fadd_rn(c, __fadd_rn(err, e));
    }
    double d = (double)s + (double)c;
    #pragma unroll
    for (int o = 16; o; o >>= 1) d += __shfl_xor_sync(0xffffffffu, d, o);
    double inv = 1.0 / fmax(sqrt(d), 1e-12);
    float ih = (float)inv;
    float il = (float)(inv - (double)ih);

    float h2[8], l2[8];
    #pragma unroll
    for (int i = 0; i < 8; i++) {
        float p = __fmul_rn(v[i], ih);
        float e = __fmaf_rn(v[i], ih, -p);
        float lo = __fmaf_rn(v[i], il, e);
        float hh = __fadd_rn(p, lo);
        h2[i] = hh;
        l2[i] = __fadd_rn(lo, -__fadd_rn(hh, -p));
    }
    float4* dh = (float4*)(g_kn_hi + (size_t)row * DKEY);
    float4* dl = (float4*)(g_kn_lo + (size_t)row * DKEY);
    dh[lane]      = make_float4(h2[0], h2[1], h2[2], h2[3]);
    dh[lane + 32] = make_float4(h2[4], h2[5], h2[6], h2[7]);
    dl[lane]      = make_float4(l2[0], l2[1], l2[2], l2[3]);
    dl[lane + 32] = make_float4(l2[4], l2[5], l2[6], l2[7]);
    __nv_bfloat162* db = (__nv_bfloat162*)(g_kb + (size_t)row * DKEY);
    db[lane*2 + 0]  = __nv_bfloat162(__float2bfloat16(h2[0]), __float2bfloat16(h2[1]));
    db[lane*2 + 1]  = __nv_bfloat162(__float2bfloat16(h2[2]), __float2bfloat16(h2[3]));
    db[64 + lane*2 + 0] = __nv_bfloat162(__float2bfloat16(h2[4]), __float2bfloat16(h2[5]));
    db[64 + lane*2 + 1] = __nv_bfloat162(__float2bfloat16(h2[6]), __float2bfloat16(h2[7]));
}

// ------------------------------ exact q GEMM v2: 32x32 tile, offset-accumulator ------------------------------
#define QTM 32
#define QTN 32
#define QTK 32
#define QOFF 1024.0f

__global__ __launch_bounds__(256) void qexact_kernel(const float* __restrict__ x,
                                                     const float* __restrict__ wq) {
    __shared__ float sX[QTK][QTM + 4];
    __shared__ float sW[QTK][QTN + 4];
    int bt = blockIdx.y * QTM;
    int bq = blockIdx.x * QTN;
    int tid = threadIdx.x;
    int ty = tid >> 4;
    int tx = tid & 15;

    float A[2][2], A2[2][2];
    #pragma unroll
    for (int i = 0; i < 2; i++)
        #pragma unroll
        for (int j = 0; j < 2; j++) { A[i][j] = QOFF; A2[i][j] = 0.f; }

    int lrow = tid >> 3;
    int lc4 = (tid & 7) * 4;

    for (int kc = 0; kc < DMODEL; kc += QTK) {
        float4 v = *(const float4*)(x + (size_t)(bt + lrow) * DMODEL + kc + lc4);
        sX[lc4+0][lrow] = v.x; sX[lc4+1][lrow] = v.y;
        sX[lc4+2][lrow] = v.z; sX[lc4+3][lrow] = v.w;
        float4 w = *(const float4*)(wq + (size_t)(bq + lrow) * DMODEL + kc + lc4);
        sW[lc4+0][lrow] = w.x; sW[lc4+1][lrow] = w.y;
        sW[lc4+2][lrow] = w.z; sW[lc4+3][lrow] = w.w;
        __syncthreads();
        #pragma unroll 8
        for (int k = 0; k < QTK; k++) {
            float2 rx = *(const float2*)&sX[k][ty * 2];
            float2 rw = *(const float2*)&sW[k][tx * 2];
            float ax[2] = {rx.x, rx.y};
            float bw[2] = {rw.x, rw.y};
            #pragma unroll
            for (int i = 0; i < 2; i++)
                #pragma unroll
                for (int j = 0; j < 2; j++) {
                    float p = __fmul_rn(ax[i], bw[j]);
                    float e = __fmaf_rn(ax[i], bw[j], -p);
                    float t = __fadd_rn(A[i][j], p);
                    float z = __fadd_rn(t, -A[i][j]);
                    float r = __fadd_rn(p, -z);
                    A[i][j] = t;
                    A2[i][j] = __fadd_rn(A2[i][j], __fadd_rn(r, e));
                }
        }
        __syncthreads();
    }

    #pragma unroll
    for (int i = 0; i < 2; i++)
        #pragma unroll
        for (int j = 0; j < 2; j++) {
            double sum = (double)__fadd_rn(A[i][j], -QOFF) + (double)A2[i][j];
            float hi = (float)sum;
            float lo = (float)(sum - (double)hi);
            g_q2[(size_t)(bt + ty*2 + i) * DKEY + (bq + tx*2 + j)] = make_float2(hi, lo);
        }
}

// ------------------------------ q normalize (fp64, ILP) ------------------------------
__global__ void qnorm_kernel() {
    int row = blockIdx.x * 8 + (threadIdx.x >> 5);
    int lane = threadIdx.x & 31;
    const float2* q = g_q2 + (size_t)row * DKEY;
    double v[8];
    double s0 = 0.0, s1 = 0.0, s2 = 0.0, s3 = 0.0;
    #pragma unroll
    for (int i = 0; i < 8; i += 4) {
        float2 p0 = q[lane + i * 32];
        float2 p1 = q[lane + (i+1) * 32];
        float2 p2 = q[lane + (i+2) * 32];
        float2 p3 = q[lane + (i+3) * 32];
        v[i]   = (double)p0.x + (double)p0.y;
        v[i+1] = (double)p1.x + (double)p1.y;
        v[i+2] = (double)p2.x + (double)p2.y;
        v[i+3] = (double)p3.x + (double)p3.y;
        s0 = fma(v[i], v[i], s0);
        s1 = fma(v[i+1], v[i+1], s1);
        s2 = fma(v[i+2], v[i+2], s2);
        s3 = fma(v[i+3], v[i+3], s3);
    }
    double ss = (s0 + s1) + (s2 + s3);
    #pragma unroll
    for (int o = 16; o; o >>= 1) ss += __shfl_xor_sync(0xffffffffu, ss, o);
    double inv = 1.0 / fmax(sqrt(ss), 1e-12);
    #pragma unroll
    for (int i = 0; i < 8; i++) {
        double qn = v[i] * inv;
        float hi = (float)qn;
        float lo = (float)(qn - (double)hi);
        size_t gi = (size_t)row * DKEY + lane + i * 32;
        g_qn_hi[gi] = hi;
        g_qn_lo[gi] = lo;
        g_qb[gi] = __float2bfloat16(hi);
    }
}

// ------------------------------ sims GEMM v1b: full-K, 128x256 tile (proven) ------------------------------
#define SBM 128
#define SBN 256
#define SPAD 264
#define SIMS_SMEM ((SBM * SPAD + SBN * SPAD) * 2)

__global__ __launch_bounds__(256, 1) void sims_kernel() {
    extern __shared__ char smem_raw[];
    bf16* sQ = (bf16*)smem_raw;
    bf16* sK = sQ + SBM * SPAD;
    float* stagef = (float*)sK;

    int bm = blockIdx.y * SBM;
    int bn = blockIdx.x * SBN;
    int tid = threadIdx.x;
    int warp = tid >> 5;
    int wr = warp >> 2;
    int wc = warp & 3;

    #pragma unroll
    for (int rep = 0; rep < 16; rep++) {
        int idx = tid + rep * 256;
        int row = idx >> 5, g = idx & 31;
        *(float4*)(sQ + row * SPAD + g * 8) =
            *(const float4*)(g_qb + (size_t)(bm + row) * DKEY + g * 8);
    }
    #pragma unroll
    for (int rep = 0; rep < 32; rep++) {
        int idx = tid + rep * 256;
        int row = idx >> 5, g = idx & 31;
        *(float4*)(sK + row * SPAD + g * 8) =
            *(const float4*)(g_kb + (size_t)(bn + row) * DKEY + g * 8);
    }
    __syncthreads();

    wmma::fragment<wmma::accumulator, 16, 16, 16, float> acc[4][4];
    #pragma unroll
    for (int i = 0; i < 4; i++)
        #pragma unroll
        for (int j = 0; j < 4; j++) wmma::fill_fragment(acc[i][j], 0.0f);

    #pragma unroll
    for (int ks = 0; ks < DKEY / 16; ks++) {
        int kc = ks * 16;
        wmma::fragment<wmma::matrix_a, 16, 16, 16, bf16, wmma::row_major> a[4];
        #pragma unroll
        for (int i = 0; i < 4; i++)
            wmma::load_matrix_sync(a[i], sQ + (wr * 64 + i * 16) * SPAD + kc, SPAD);
        #pragma unroll
        for (int half = 0; half < 2; half++) {
            wmma::fragment<wmma::matrix_b, 16, 16, 16, bf16, wmma::col_major> b[2];
            #pragma unroll
            for (int jj = 0; jj < 2; jj++)
                wmma::load_matrix_sync(b[jj], sK + (wc * 64 + (half * 2 + jj) * 16) * SPAD + kc, SPAD);
            #pragma unroll
            for (int i = 0; i < 4; i++)
                #pragma unroll
                for (int jj = 0; jj < 2; jj++)
                    wmma::mma_sync(acc[i][half * 2 + jj], a[i], b[jj], acc[i][half * 2 + jj]);
        }
    }
    __syncthreads();

    #pragma unroll
    for (int i = 0; i < 4; i++)
        #pragma unroll
        for (int j = 0; j < 4; j++)
            wmma::store_matrix_sync(stagef + (wr * 64 + i * 16) * 260 + wc * 64 + j * 16,
                                    acc[i][j], 260, wmma::mem_row_major);
    __syncthreads();

    #pragma unroll
    for (int rep = 0; rep < 16; rep++) {
        int idx = tid + rep * 256;
        int row = idx >> 5, g = idx & 31;
        const float* src = stagef + row * 260 + g * 8;
        float4 f0 = *(const float4*)src;
        float4 f1 = *(const float4*)(src + 4);
        __align__(16) bf16 tmp[8];
        tmp[0] = __float2bfloat16(f0.x); tmp[1] = __float2bfloat16(f0.y);
        tmp[2] = __float2bfloat16(f0.z); tmp[3] = __float2bfloat16(f0.w);
        tmp[4] = __float2bfloat16(f1.x); tmp[5] = __float2bfloat16(f1.y);
        tmp[6] = __float2bfloat16(f1.z); tmp[7] = __float2bfloat16(f1.w);
        *(float4*)(g_sims + (size_t)(bm + row) * NMEM + bn + g * 8) = *(float4*)tmp;

        float mx = __bfloat162float(tmp[0]);
        #pragma unroll
        for (int e = 1; e < 8; e++) mx = fmaxf(mx, __bfloat162float(tmp[e]));
        #pragma unroll
        for (int off = 1; off < 8; off <<= 1)
            mx = fmaxf(mx, __shfl_xor_sync(0xffffffffu, mx, off));
        if ((g & 7) == 0)
            g_blkmax[(size_t)(bm + row) * NCHUNK + (bn >> 6) + (g >> 3)] = __float2bfloat16(mx);
    }
}

// ------------------------------ top-64 preselect v3: chunk-max pruning ------------------------------
__device__ __forceinline__ unsigned ordkey16(unsigned u) {
    return (u & 0x8000u) ? (u ^ 0xFFFFu) : (u | 0x8000u);
}

__global__ __launch_bounds__(256) void topk_kernel() {
    int t = blockIdx.x;
    extern __shared__ unsigned short sbuf[];
    __shared__ unsigned short sclist[NCHUNK];
    __shared__ unsigned hist[256];
    __shared__ unsigned sh_b, sh_above, sh_KM, sh_nsel, sh_thr, sh_K1, ctrG, ctrE;
    int tid = threadIdx.x;

    hist[tid] = 0;
    __syncthreads();
    unsigned mk0, mk1;
    {
        const unsigned short* bm = (const unsigned short*)(g_blkmax + (size_t)t * NCHUNK);
        mk0 = ordkey16((unsigned)bm[tid]);
        mk1 = ordkey16((unsigned)bm[tid + 256]);
        atomicAdd(&hist[mk0 >> 8], 1u);
        atomicAdd(&hist[mk1 >> 8], 1u);
    }
    __syncthreads();
    if (tid == 0) {
        unsigned cum = 0; int b = 255;
        for (; b > 0; b--) { if (cum + hist[b] >= NCAND) break; cum += hist[b]; }
        sh_b = (unsigned)b; sh_above = cum;
    }
    __syncthreads();
    unsigned b = sh_b;
    hist[tid] = 0;
    __syncthreads();
    if ((mk0 >> 8) == b) atomicAdd(&hist[mk0 & 255u], 1u);
    if ((mk1 >> 8) == b) atomicAdd(&hist[mk1 & 255u], 1u);
    __syncthreads();
    if (tid == 0) {
        unsigned cum = sh_above; int l = 255;
        for (; l > 0; l--) { if (cum + hist[l] >= NCAND) break; cum += hist[l]; }
        sh_KM = (b << 8) | (unsigned)l;
        sh_nsel = 0;
    }
    __syncthreads();

    unsigned KM = sh_KM;
    if (mk0 >= KM) { unsigned p = atomicAdd(&sh_nsel, 1u); sclist[p] = (unsigned short)tid; }
    if (mk1 >= KM) { unsigned p = atomicAdd(&sh_nsel, 1u); sclist[p] = (unsigned short)(tid + 256); }
    __syncthreads();
    int ns = (int)sh_nsel * 64;

    hist[tid] = 0;
    __syncthreads();
    const unsigned short* row = (const unsigned short*)(g_sims + (size_t)t * NMEM);
    for (int j = tid; j < ns; j += 256) {
        int chunk = sclist[j >> 6];
        unsigned k = ordkey16((unsigned)row[chunk * 64 + (j & 63)]);
        if (j < TKCAP) sbuf[j] = (unsigned short)k;
        atomicAdd(&hist[k >> 8], 1u);
    }
    __syncthreads();
    if (tid == 0) {
        unsigned cum = 0; int bb = 255;
        for (; bb > 0; bb--) { if (cum + hist[bb] >= NCAND) break; cum += hist[bb]; }
        sh_b = (unsigned)bb; sh_above = cum;
    }
    __syncthreads();
    unsigned b2 = sh_b;
    hist[tid] = 0;
    __syncthreads();
    for (int j = tid; j < ns; j += 256) {
        unsigned k = (j < TKCAP) ? (unsigned)sbuf[j]
                   : ordkey16((unsigned)row[sclist[j >> 6] * 64 + (j & 63)]);
        if ((k >> 8) == b2) atomicAdd(&hist[k & 255u], 1u);
    }
    __syncthreads();
    if (tid == 0) {
        unsigned cum = sh_above; int l = 255;
        for (; l > 0; l--) { if (cum + hist[l] >= NCAND) break; cum += hist[l]; }
        sh_thr = (b2 << 8) | (unsigned)l;
        sh_K1 = cum;
        ctrG = 0; ctrE = 0;
    }
    __syncthreads();

    unsigned thr = sh_thr, K1 = sh_K1;
    for (int j = tid; j < ns; j += 256) {
        unsigned k = (j < TKCAP) ? (unsigned)sbuf[j]
                   : ordkey16((unsigned)row[sclist[j >> 6] * 64 + (j & 63)]);
        if (k > thr) {
            unsigned p = atomicAdd(&ctrG, 1u);
            g_cand[t * NCAND + p] = (int)sclist[j >> 6] * 64 + (j & 63);
        } else if (k == thr) {
            unsigned p = atomicAdd(&ctrE, 1u);
            if (K1 + p < NCAND) g_cand[t * NCAND + K1 + p] = (int)sclist[j >> 6] * 64 + (j & 63);
        }
    }
}

// ------------------------------ fused: exact rescore + top-32 + softmax + gather ------------------------------
__device__ __forceinline__ void kmac(float a, float b, float& s, float& c) {
    float p  = __fmul_rn(a, b);
    float e  = __fmaf_rn(a, b, -p);
    float t  = __fadd_rn(s, p);
    float bv = __fadd_rn(t, -s);
    float e1 = __fadd_rn(s, -__fadd_rn(t, -bv));
    float e2 = __fadd_rn(p, -bv);
    s = t;
    c = __fadd_rn(c, __fadd_rn(e, __fadd_rn(e1, e2)));
}

__global__ __launch_bounds__(256) void rescore_gather_kernel(const float* __restrict__ values) {
    int t = blockIdx.x;
    int tid = threadIdx.x;
    __shared__ __align__(16) float qhi[DKEY];
    __shared__ __align__(16) float qlo[DKEY];
    __shared__ float cval[NCAND];
    __shared__ int cidx[NCAND];
    __shared__ float sw[TOPK];
    __shared__ int sidx[TOPK];
    __shared__ float sval[TOPK];

    qhi[tid] = g_qn_hi[(size_t)t * DKEY + tid];
    qlo[tid] = g_qn_lo[(size_t)t * DKEY + tid];
    if (tid < NCAND) cidx[tid] = g_cand[t * NCAND + tid];
    __syncthreads();

    int c = tid >> 2, part = tid & 3;
    int ki = cidx[c];
    const float* khi = g_kn_hi + (size_t)ki * DKEY + part * 64;
    const float* klo = g_kn_lo + (size_t)ki * DKEY + part * 64;
    const float* qh = qhi + part * 64;
    const float* ql = qlo + part * 64;

    float s = 0.f, comp = 0.f, cr = 0.f;
    #pragma unroll 8
    for (int i = 0; i < 64; i++) {
        float kh = khi[i], kl = klo[i];
        float qhv = qh[i], qlv = ql[i];
        kmac(qhv, kh, s, comp);
        cr = __fmaf_rn(qhv, kl, cr);
        cr = __fmaf_rn(qlv, kh, cr);
    }
    double v = (double)s + (double)comp + (double)cr;
    v += __shfl_xor_sync(0xffffffffu, v, 1);
    v += __shfl_xor_sync(0xffffffffu, v, 2);
    if (part == 0) cval[c] = (float)v;
    __syncthreads();

    if (tid < NCAND) {
        float val = cval[tid]; int myi = cidx[tid];
        int rnk = 0;
        #pragma unroll 8
        for (int j = 0; j < NCAND; j++) {
            float u = cval[j];
            rnk += (u > val) || (u == val && cidx[j] < myi);
        }
        if (rnk < TOPK) { sval[rnk] = val; sidx[rnk] = myi; }
    }
    __syncthreads();

    if (tid < 32) {
        float val = sval[tid];
        float m = val;
        #pragma unroll
        for (int o = 16; o; o >>= 1) m = fmaxf(m, __shfl_xor_sync(0xffffffffu, m, o));
        float e = expf(val - m);
        float sum = e;
        #pragma unroll
        for (int o = 16; o; o >>= 1) sum += __shfl_xor_sync(0xffffffffu, sum, o);
        sw[tid] = e / sum;
    }
    __syncthreads();

    float4 acc = make_float4(0.f, 0.f, 0.f, 0.f);
    #pragma unroll 8
    for (int i = 0; i < TOPK; i++) {
        const float4 vv = *((const float4*)(values + (size_t)sidx[i] * DVAL) + tid);
        float wi = sw[i];
        acc.x = fmaf(wi, vv.x, acc.x);
        acc.y = fmaf(wi, vv.y, acc.y);
        acc.z = fmaf(wi, vv.z, acc.z);
        acc.w = fmaf(wi, vv.w, acc.w);
    }
    ((float4*)(g_memout + (size_t)t * DVAL))[tid] = acc;
}

// ------------------------------ h epilogue: h = silu(gpre) * memout -> hhi/hlo ------------------------------
__global__ void hepi_kernel() {
    int i = blockIdx.x * blockDim.x + threadIdx.x;
    float4 g = ((const float4*)g_gpre)[i];
    float4 m = ((const float4*)g_memout)[i];
    float hv[4];
    hv[0] = (g.x / (1.0f + expf(-g.x))) * m.x;
    hv[1] = (g.y / (1.0f + expf(-g.y))) * m.y;
    hv[2] = (g.z / (1.0f + expf(-g.z))) * m.z;
    hv[3] = (g.w / (1.0f + expf(-g.w))) * m.w;
    __align__(8) bf16 hh[4], hl[4];
    #pragma unroll
    for (int e = 0; e < 4; e++) {
        bf16 h = __float2bfloat16(hv[e]);
        hh[e] = h;
        hl[e] = __float2bfloat16(__fadd_rn(hv[e], -__bfloat162float(h)));
    }
    *(float2*)(g_hhi + (size_t)i * 4) = *(float2*)hh;
    *(float2*)(g_hlo + (size_t)i * 4) = *(float2*)hl;
}

// ------------------------------ 3-term split-bf16 GEMM, double-buffered, conflict-free stride 24 ------------------------------
// WHICH: 1 = gate matmul (A=x, B=w_gate) -> g_gpre;  2 = out (A=h, B=w_out) -> Cout
#define GROW 24                       // smem row stride in bf16 (48 B: conflict-free LDSM)
#define GSTAGE ((128 + 128 + 64 + 64) * GROW)   // 9216 bf16 per stage

template<int WHICH>
__global__ __launch_bounds__(256) void gemm_kernel(float* __restrict__ Cout) {
    constexpr int N = (WHICH == 1) ? DVAL : DMODEL;
    constexpr int K = (WHICH == 2) ? DVAL : DMODEL;
    constexpr int BM = 128, BN = 64, KC = 16;
    constexpr int NIT = K / KC;

    const bf16* Ahi = (WHICH == 2) ? g_hhi : g_xhi;
    const bf16* Alo = (WHICH == 2) ? g_hlo : g_xlo;
    const bf16* Bhi = (WHICH == 1) ? g_wghi : g_wohi;
    const bf16* Blo = (WHICH == 1) ? g_wglo : g_wolo;

    extern __shared__ char smem_raw[];
    bf16* sbuf = (bf16*)smem_raw;      // 2 stages x GSTAGE bf16 = 36864 B

    int bm = blockIdx.y * BM;
    int bn = blockIdx.x * BN;
    int tid = threadIdx.x;
    int warp = tid >> 5;
    int wr = warp >> 1;
    int wc = warp & 1;

    wmma::fragment<wmma::accumulator, 16, 16, 16, float> acc[2][2];
    #pragma unroll
    for (int i = 0; i < 2; i++)
        #pragma unroll
        for (int j = 0; j < 2; j++) wmma::fill_fragment(acc[i][j], 0.0f);

    int ar = tid >> 1, ah = (tid & 1) * 8;
    int br = tid >> 2, bh2 = (tid & 3);

    const int OAH = 0, OAL = 128 * GROW, OBH = 256 * GROW, OBL = 320 * GROW;

    {
        const float4 va = *(const float4*)(Ahi + (size_t)(bm + ar) * K + ah);
        const float4 vb = *(const float4*)(Alo + (size_t)(bm + ar) * K + ah);
        *(float4*)(sbuf + OAH + ar * GROW + ah) = va;
        *(float4*)(sbuf + OAL + ar * GROW + ah) = vb;
        const bf16* bsrc = (bh2 & 2) ? Blo : Bhi;
        int bofs = (bh2 & 1) * 8;
        const float4 vc = *(const float4*)(bsrc + (size_t)(bn + br) * K + bofs);
        *(float4*)(sbuf + ((bh2 & 2) ? OBL : OBH) + br * GROW + bofs) = vc;
    }
    __syncthreads();

    #pragma unroll 4
    for (int it = 0; it < NIT; it++) {
        int cur = (it & 1) * GSTAGE;
        float4 pa, pal, pb;
        if (it + 1 < NIT) {
            int kc = (it + 1) * KC;
            pa  = *(const float4*)(Ahi + (size_t)(bm + ar) * K + kc + ah);
            pal = *(const float4*)(Alo + (size_t)(bm + ar) * K + kc + ah);
            const bf16* bsrc = (bh2 & 2) ? Blo : Bhi;
            pb  = *(const float4*)(bsrc + (size_t)(bn + br) * K + kc + (bh2 & 1) * 8);
        }

        wmma::fragment<wmma::matrix_a, 16, 16, 16, bf16, wmma::row_major> a0, a1, c0, c1;
        wmma::fragment<wmma::matrix_b, 16, 16, 16, bf16, wmma::col_major> b0, b1;

        wmma::load_matrix_sync(a0, sbuf + cur + OAH + (wr * 32 + 0) * GROW, GROW);
        wmma::load_matrix_sync(a1, sbuf + cur + OAH + (wr * 32 + 16) * GROW, GROW);
        wmma::load_matrix_sync(b0, sbuf + cur + OBH + (wc * 32 + 0) * GROW, GROW);
        wmma::load_matrix_sync(b1, sbuf + cur + OBH + (wc * 32 + 16) * GROW, GROW);
        wmma::mma_sync(acc[0][0], a0, b0, acc[0][0]);
        wmma::mma_sync(acc[0][1], a0, b1, acc[0][1]);
        wmma::mma_sync(acc[1][0], a1, b0, acc[1][0]);
        wmma::mma_sync(acc[1][1], a1, b1, acc[1][1]);

        wmma::load_matrix_sync(c0, sbuf + cur + OAL + (wr * 32 + 0) * GROW, GROW);
        wmma::load_matrix_sync(c1, sbuf + cur + OAL + (wr * 32 + 16) * GROW, GROW);
        wmma::mma_sync(acc[0][0], c0, b0, acc[0][0]);
        wmma::mma_sync(acc[0][1], c0, b1, acc[0][1]);
        wmma::mma_sync(acc[1][0], c1, b0, acc[1][0]);
        wmma::mma_sync(acc[1][1], c1, b1, acc[1][1]);

        wmma::load_matrix_sync(b0, sbuf + cur + OBL + (wc * 32 + 0) * GROW, GROW);
        wmma::load_matrix_sync(b1, sbuf + cur + OBL + (wc * 32 + 16) * GROW, GROW);
        wmma::mma_sync(acc[0][0], a0, b0, acc[0][0]);
        wmma::mma_sync(acc[0][1], a0, b1, acc[0][1]);
        wmma::mma_sync(acc[1][0], a1, b0, acc[1][0]);
        wmma::mma_sync(acc[1][1], a1, b1, acc[1][1]);

        if (it + 1 < NIT) {
            int nxt = ((it + 1) & 1) * GSTAGE;
            *(float4*)(sbuf + nxt + OAH + ar * GROW + ah) = pa;
            *(float4*)(sbuf + nxt + OAL + ar * GROW + ah) = pal;
            *(float4*)(sbuf + nxt + ((bh2 & 2) ? OBL : OBH) + br * GROW + (bh2 & 1) * 8) = pb;
            __syncthreads();
        }
    }

    #pragma unroll
    for (int i = 0; i < 2; i++)
        #pragma unroll
        for (int j = 0; j < 2; j++)
            wmma::store_matrix_sync(Cout + (size_t)(bm + wr * 32 + i * 16) * N + bn + wc * 32 + j * 16,
                                    acc[i][j], N, wmma::mem_row_major);
}

// ------------------------------ streams / events (host objects, static init) ------------------------------
static cudaStream_t g_s2;
static cudaEvent_t g_evFork, g_evK, g_evG;
namespace {
struct StreamInit {
    StreamInit() {
        cudaStreamCreateWithFlags(&g_s2, cudaStreamNonBlocking);
        cudaEventCreateWithFlags(&g_evFork, cudaEventDisableTiming);
        cudaEventCreateWithFlags(&g_evK, cudaEventDisableTiming);
        cudaEventCreateWithFlags(&g_evG, cudaEventDisableTiming);
    }
};
StreamInit g_si;
}

// ------------------------------ launcher (2-stream overlap) ------------------------------
extern "C" void kernel_launch(void* const* d_in, const int* in_sizes, int n_in,
                              void* d_out, int out_size) {
    const float *x = nullptr, *keys = nullptr, *values = nullptr,
                *w_q = nullptr, *w_gate = nullptr, *w_out = nullptr;
    for (int i = 0; i < n_in; i++) {
        int sz = in_sizes[i];
        const float* p = (const float*)d_in[i];
        if (sz == BS_TOK * DMODEL)      x = p;
        else if (sz == NMEM * DKEY)     keys = p;
        else if (sz == NMEM * DVAL)     values = p;
        else if (sz == DKEY * DMODEL)   w_q = p;
        else if (sz == DVAL * DMODEL) { if (!w_gate) w_gate = p; else w_out = p; }
    }
    float* out = (float*)d_out;
    float* gpre;
    cudaGetSymbolAddress((void**)&gpre, g_gpre);

    cudaFuncSetAttribute(sims_kernel, cudaFuncAttributeMaxDynamicSharedMemorySize, SIMS_SMEM);

    size_t smem_g = 2 * GSTAGE * sizeof(bf16);  // 36864 B
    size_t smem_tk = TKCAP * 2;                 // 16384 B

    // fork side stream
    cudaEventRecord(g_evFork, 0);
    cudaStreamWaitEvent(g_s2, g_evFork, 0);

    // side stream: knorm (feeds sims), then splits + gate matmul (feeds hepi)
    knorm_kernel<<<NMEM / 8, 256, 0, g_s2>>>(keys);
    cudaEventRecord(g_evK, g_s2);
    splitx_kernel<<<(NX + 255) / 256, 256, 0, g_s2>>>(x);
    splitw_kernel<<<(NWG + NWO + 255) / 256, 256, 0, g_s2>>>(w_gate, w_out);
    gemm_kernel<1><<<dim3(DVAL / 64, BS_TOK / 128), 256, smem_g, g_s2>>>(gpre);
    cudaEventRecord(g_evG, g_s2);

    // main stream: critical path
    qexact_kernel<<<dim3(DKEY / QTN, BS_TOK / QTM), 256>>>(x, w_q);
    qnorm_kernel<<<BS_TOK / 8, 256>>>();
    cudaStreamWaitEvent(0, g_evK, 0);
    sims_kernel<<<dim3(NMEM / SBN, BS_TOK / SBM), 256, SIMS_SMEM>>>();
    topk_kernel<<<BS_TOK, 256, smem_tk>>>();
    rescore_gather_kernel<<<BS_TOK, 256>>>(values);
    cudaStreamWaitEvent(0, g_evG, 0);
    hepi_kernel<<<BS_TOK * DVAL / 4 / 256, 256>>>();
    gemm_kernel<2><<<dim3(DMODEL / 64, BS_TOK / 128), 256, smem_g>>>(out);
}